// round 13
// baseline (speedup 1.0000x reference)
#include <cuda_runtime.h>
#include <cuda_bf16.h>
#include <math.h>
#include <stdint.h>

#define BB 128
#define TT 256
#define FF 64
#define HH 512
#define G4 2048
#define NBLK 128  // persistent LSTM grid

// ---------------- mma / ldmatrix / cp.async helpers (arch-generic) ----------
__device__ __forceinline__ void mma_bf16(float* d, const uint32_t* a, const uint32_t* b) {
    asm volatile(
        "mma.sync.aligned.m16n8k16.row.col.f32.bf16.bf16.f32 "
        "{%0,%1,%2,%3}, {%4,%5,%6,%7}, {%8,%9}, {%0,%1,%2,%3};"
        : "+f"(d[0]), "+f"(d[1]), "+f"(d[2]), "+f"(d[3])
        : "r"(a[0]), "r"(a[1]), "r"(a[2]), "r"(a[3]), "r"(b[0]), "r"(b[1]));
}
__device__ __forceinline__ void ldsm4(uint32_t* r, uint32_t addr) {
    asm volatile("ldmatrix.sync.aligned.m8n8.x4.shared.b16 {%0,%1,%2,%3}, [%4];"
        : "=r"(r[0]), "=r"(r[1]), "=r"(r[2]), "=r"(r[3]) : "r"(addr));
}
__device__ __forceinline__ uint32_t smem_u32(const void* p) {
    uint32_t a;
    asm("{ .reg .u64 t; cvta.to.shared.u64 t, %1; cvt.u32.u64 %0, t; }"
        : "=r"(a) : "l"(p));
    return a;
}
__device__ __forceinline__ void cp16(uint32_t dst, const void* src) {
    asm volatile("cp.async.cg.shared.global [%0], [%1], 16;"
        :: "r"(dst), "l"(src) : "memory");
}
#define CP_COMMIT() asm volatile("cp.async.commit_group;" ::: "memory")
#define CP_WAIT0()  asm volatile("cp.async.wait_group 0;" ::: "memory")

__device__ __forceinline__ void bsplit(float w, __nv_bfloat16* hi, __nv_bfloat16* lo) {
    __nv_bfloat16 h = __float2bfloat16(w);
    *hi = h;
    *lo = __float2bfloat16(w - __bfloat162float(h));
}
__device__ __forceinline__ float fsigm(float x) {
    return __fdividef(1.f, 1.f + __expf(-x));
}
__device__ __forceinline__ float ftanh(float x) {
    x = fminf(fmaxf(x, -15.f), 15.f);
    float e = __expf(-2.f * x);
    return __fdividef(1.f - e, 1.f + e);
}

// ---------------- scratch ----------------
__device__ __nv_bfloat16 g_hh[BB * TT * HH], g_hl[BB * TT * HH];
__device__ __nv_bfloat16 g_sh[BB * TT * HH], g_sl[BB * TT * HH];
__device__ __nv_bfloat16 g_Wxh[2][G4 * HH], g_Wxl[2][G4 * HH];
__device__ float g_xg[(size_t)BB * TT * G4];
__device__ __nv_bfloat16 g_hpA[BB * HH], g_hpB[BB * HH];
__device__ __nv_bfloat16 g_lpA[BB * HH], g_lpB[BB * HH];
__device__ float g_hfin[BB * HH];
__device__ float g_ln[BB * HH];
__device__ float g_d2[BB * (HH / 2)];
__device__ unsigned g_cnt4[4];
__device__ unsigned g_gen4[4];

// ------- per-batch-group grid barrier: release-arrive / acquire-spin --------
__device__ __forceinline__ void grid_bar4(int grp) {
    __syncthreads();
    if (threadIdx.x == 0) {
        unsigned* cp = &g_cnt4[grp];
        unsigned* gp = &g_gen4[grp];
        unsigned gen;
        asm volatile("ld.acquire.gpu.u32 %0, [%1];" : "=r"(gen) : "l"(gp));
        unsigned old;
        asm volatile("atom.add.release.gpu.u32 %0, [%1], 1;" : "=r"(old) : "l"(cp) : "memory");
        if (old == 31u) {
            asm volatile("st.relaxed.gpu.u32 [%0], 0;" :: "l"(cp) : "memory");
            asm volatile("red.add.release.gpu.u32 [%0], 1;" :: "l"(gp) : "memory");
        } else {
            unsigned g2;
            do {
                asm volatile("ld.acquire.gpu.u32 %0, [%1];" : "=r"(g2) : "l"(gp));
            } while (g2 == gen);
        }
    }
    __syncthreads();
}

// ---------------- dense1 + L2-norm scale (writes bf16 splits) ---------------
__global__ void dense1_norm(const float* __restrict__ x, const float* __restrict__ W1,
                            const float* __restrict__ b1) {
    __shared__ float xs[16][FF];
    __shared__ float hs[16][HH];
    const int tid = threadIdx.x;
    const int m0 = blockIdx.x * 16;
    for (int i = tid; i < 16 * FF; i += 256)
        xs[i / FF][i % FF] = x[(m0 + i / FF) * FF + i % FF];
    __syncthreads();
    const int c0 = tid * 2;
    float a0[16], a1[16];
#pragma unroll
    for (int r = 0; r < 16; r++) { a0[r] = 0.f; a1[r] = 0.f; }
    for (int k = 0; k < FF; k++) {
        float w0 = W1[k * HH + c0], w1 = W1[k * HH + c0 + 1];
#pragma unroll
        for (int r = 0; r < 16; r++) { float xv = xs[r][k]; a0[r] += xv * w0; a1[r] += xv * w1; }
    }
    float bb0 = b1[c0], bb1 = b1[c0 + 1];
#pragma unroll
    for (int r = 0; r < 16; r++) { hs[r][c0] = a0[r] + bb0; hs[r][c0 + 1] = a1[r] + bb1; }
    __syncthreads();
    int wid = tid >> 5, lane = tid & 31;
#pragma unroll
    for (int rr = 0; rr < 2; rr++) {
        int r = wid * 2 + rr;
        float ss = 0.f;
        for (int c = lane; c < HH; c += 32) { float v = hs[r][c]; ss += v * v; }
#pragma unroll
        for (int o = 16; o; o >>= 1) ss += __shfl_xor_sync(0xffffffffu, ss, o);
        float sc = sqrtf((float)HH) / fmaxf(sqrtf(ss), 1e-12f);
        for (int c = lane; c < HH; c += 32) {
            float v = hs[r][c] * sc;
            __nv_bfloat16 vh, vl;
            bsplit(v, &vh, &vl);
            g_hh[(size_t)(m0 + r) * HH + c] = vh;
            g_hl[(size_t)(m0 + r) * HH + c] = vl;
        }
    }
}

// ---------------- Wx -> transposed bf16 splits [n][k], tiled ----------------
__global__ void convW(const float* __restrict__ W, int layer) {
    __shared__ float tile[32][33];
    const int tx = threadIdx.x & 31, ty4 = (threadIdx.x >> 5) * 4;
    const int n0 = blockIdx.x * 32, k0 = blockIdx.y * 32;
#pragma unroll
    for (int r = 0; r < 4; r++)
        tile[ty4 + r][tx] = W[(size_t)(k0 + ty4 + r) * G4 + n0 + tx];
    __syncthreads();
#pragma unroll
    for (int r = 0; r < 4; r++) {
        int n = n0 + ty4 + r;
        float w = tile[tx][ty4 + r];
        __nv_bfloat16 h_, l_;
        bsplit(w, &h_, &l_);
        g_Wxh[layer][(size_t)n * HH + k0 + tx] = h_;
        g_Wxl[layer][(size_t)n * HH + k0 + tx] = l_;
    }
}

// ---------------- xg GEMM: 256 thr, 8 warps (4m x 2n), warp 32x64, Kc=32 ----
// single __syncthreads per chunk: wait -> sync -> issue next -> compute
#define XS_ROW   80                    // 32 bf16 (64B) + 16B pad
#define XS_ARR   (128 * XS_ROW)        // 10240
#define XS_STAGE (4 * XS_ARR)          // 40960
#define XS_SMEM  (2 * XS_STAGE)        // 81920

__global__ void __launch_bounds__(256, 2) gemm_xg(int layer, const float* __restrict__ bias) {
    const __nv_bfloat16* __restrict__ Ah = layer ? g_sh : g_hh;
    const __nv_bfloat16* __restrict__ Al = layer ? g_sl : g_hl;
    const __nv_bfloat16* __restrict__ Bh = g_Wxh[layer];
    const __nv_bfloat16* __restrict__ Bl = g_Wxl[layer];

    extern __shared__ __align__(16) uint8_t smd[];
    const int tid = threadIdx.x;
    const int lane = tid & 31, wid = tid >> 5;
    const int n0 = blockIdx.x * 128, m0 = blockIdx.y * 128;
    const int m_off = (wid >> 1) * 32, n_off = (wid & 1) * 64;
    const int lr = lane >> 2, lc = (lane & 3) * 2;

    float acc[2][8][4];
#pragma unroll
    for (int i = 0; i < 2; i++)
#pragma unroll
        for (int j = 0; j < 8; j++)
#pragma unroll
            for (int q = 0; q < 4; q++) acc[i][j][q] = 0.f;

    const uint32_t smb = smem_u32(smd);
    const __nv_bfloat16* srcs[8];
    uint32_t dsts[8];
#pragma unroll
    for (int j = 0; j < 8; j++) {
        int id = tid + 256 * j;
        int arr = id >> 9, row = (id >> 2) & 127, seg = id & 3;
        const __nv_bfloat16* base =
            (arr == 0 ? Ah + (size_t)(m0 + row) * HH :
             arr == 1 ? Al + (size_t)(m0 + row) * HH :
             arr == 2 ? Bh + (size_t)(n0 + row) * HH :
                        Bl + (size_t)(n0 + row) * HH);
        srcs[j] = base + seg * 8;
        dsts[j] = smb + arr * XS_ARR + row * XS_ROW + seg * 16;
    }

#pragma unroll
    for (int j = 0; j < 8; j++) cp16(dsts[j], srcs[j]);
    CP_COMMIT();

    int s = 0;
    for (int kc = 0; kc < HH; kc += 32) {
        CP_WAIT0();
        __syncthreads();
        // issue next chunk into s^1 (safe: prior reads of s^1 finished before
        // every thread passed the barrier above)
        if (kc + 32 < HH) {
#pragma unroll
            for (int j = 0; j < 8; j++) cp16(dsts[j] + (s ^ 1) * XS_STAGE, srcs[j] + kc + 32);
            CP_COMMIT();
        }
        const uint32_t sb = smb + s * XS_STAGE;

#pragma unroll
        for (int ks = 0; ks < 32; ks += 16) {
            uint32_t afh[2][4], afl[2][4];
#pragma unroll
            for (int mi = 0; mi < 2; mi++) {
                uint32_t ar = sb + (m_off + mi * 16 + (lane & 15)) * XS_ROW +
                              ks * 2 + (lane >> 4) * 16;
                ldsm4(afh[mi], ar);
                ldsm4(afl[mi], ar + XS_ARR);
            }
            uint32_t bfh[8][2], bfl[8][2];
#pragma unroll
            for (int g = 0; g < 4; g++) {
                uint32_t br = sb + 2 * XS_ARR + (n_off + g * 16 + (lane & 15)) * XS_ROW +
                              ks * 2 + (lane >> 4) * 16;
                uint32_t tt[4];
                ldsm4(tt, br);
                bfh[2 * g][0] = tt[0]; bfh[2 * g + 1][0] = tt[1];
                bfh[2 * g][1] = tt[2]; bfh[2 * g + 1][1] = tt[3];
                ldsm4(tt, br + XS_ARR);
                bfl[2 * g][0] = tt[0]; bfl[2 * g + 1][0] = tt[1];
                bfl[2 * g][1] = tt[2]; bfl[2 * g + 1][1] = tt[3];
            }
#pragma unroll
            for (int mi = 0; mi < 2; mi++)
#pragma unroll
                for (int nf = 0; nf < 8; nf++) {
                    mma_bf16(acc[mi][nf], afh[mi], bfh[nf]);
                    mma_bf16(acc[mi][nf], afh[mi], bfl[nf]);
                    mma_bf16(acc[mi][nf], afl[mi], bfh[nf]);
                }
        }
        s ^= 1;
    }

#pragma unroll
    for (int mi = 0; mi < 2; mi++)
#pragma unroll
        for (int nf = 0; nf < 8; nf++) {
            int r = m0 + m_off + mi * 16 + lr;
            int c = n0 + n_off + nf * 8 + lc;
            float2 bv = *(const float2*)&bias[c];
            *(float2*)&g_xg[(size_t)r * G4 + c] =
                make_float2(acc[mi][nf][0] + bv.x, acc[mi][nf][1] + bv.y);
            *(float2*)&g_xg[(size_t)(r + 8) * G4 + c] =
                make_float2(acc[mi][nf][2] + bv.x, acc[mi][nf][3] + bv.y);
        }
}

// ---------------- zero initial h splits ----------------
__global__ void zero_h() {
    int i = blockIdx.x * 256 + threadIdx.x;
    if (i < BB * HH / 2) {
        ((unsigned*)g_hpA)[i] = 0u;
        ((unsigned*)g_lpA)[i] = 0u;
    }
}

// ==================== persistent mma.sync LSTM (512 thr, K-split) ===========
// 128 blocks; block = 32 batch x 64 gate-cols. Warps 0-7: K[0,256), 8-15: K[256,512).
// (Round-11 proven structure; xg for t+1 prefetched before the grid barrier.)
#define L_BHI 0
#define L_BLO 66560
#define L_AHI 133120
#define L_ALO 166400
#define L_GS  199680
#define L_SMEM 216320

__global__ void __launch_bounds__(512, 1)
lstm_mma(const float* __restrict__ Wh, int layer) {
    extern __shared__ __align__(16) uint8_t sm[];
    const int tid = threadIdx.x, lane = tid & 31, wid = tid >> 5;
    const int grp = blockIdx.x >> 5;
    const int b0 = grp * 32;
    const int j0 = (blockIdx.x & 31) * 16;
    const int kh = wid >> 3;
    const int wq = wid & 7;
    const int m_off = (wq >> 2) * 16, n_off = (wq & 3) * 16;
    const int lr = lane >> 2, lc = (lane & 3) * 2;

    for (int i = tid; i < 64 * HH; i += 512) {
        int n = i & 63, k = i >> 6;
        float w = Wh[k * G4 + (n >> 4) * HH + j0 + (n & 15)];
        __nv_bfloat16 h_, l_;
        bsplit(w, &h_, &l_);
        *(__nv_bfloat16*)(sm + L_BHI + ((size_t)n * 520 + k) * 2) = h_;
        *(__nv_bfloat16*)(sm + L_BLO + ((size_t)n * 520 + k) * 2) = l_;
    }
    __syncthreads();

    float* Gs = (float*)(sm + L_GS);
    const uint32_t smb = smem_u32(sm);
    const int rr = tid >> 4, jj = tid & 15;
    const int tidl = tid & 255;
    const int kbase = kh * 256;
    float creg = 0.f;

    const uint32_t rAh = smb + L_AHI + (m_off + (lane & 15)) * 1040 + (lane >> 4) * 16 + kh * 512;
    const uint32_t rAl = smb + L_ALO + (m_off + (lane & 15)) * 1040 + (lane >> 4) * 16 + kh * 512;
    const uint32_t rBh = smb + L_BHI + (n_off + (lane & 15)) * 1040 + (lane >> 4) * 16 + kh * 512;
    const uint32_t rBl = smb + L_BLO + (n_off + (lane & 15)) * 1040 + (lane >> 4) * 16 + kh * 512;

    // prefetch xg for t=0
    float x0, x1, x2, x3;
    {
        const float* xb = g_xg + ((size_t)(b0 + rr) * TT + 0) * G4 + j0 + jj;
        x0 = xb[0]; x1 = xb[512]; x2 = xb[1024]; x3 = xb[1536];
    }

    for (int t = 0; t < TT; t++) {
        const __nv_bfloat16* hph = (t & 1) ? g_hpB : g_hpA;
        const __nv_bfloat16* hpl = (t & 1) ? g_lpB : g_lpA;

        // each K-half warp-group loads ONLY its own half of the h tile
#pragma unroll
        for (int idx = tidl; idx < 1024; idx += 256) {
            int row = idx >> 5, k8 = (idx & 31) * 8 + kbase;
            cp16(smb + L_AHI + row * 1040 + k8 * 2, hph + (size_t)(b0 + row) * HH + k8);
            cp16(smb + L_ALO + row * 1040 + k8 * 2, hpl + (size_t)(b0 + row) * HH + k8);
        }
        CP_COMMIT();
        CP_WAIT0();
        asm volatile("bar.sync %0, 256;" :: "r"(4 + kh) : "memory");

        float acc[2][4] = {{0.f, 0.f, 0.f, 0.f}, {0.f, 0.f, 0.f, 0.f}};
#pragma unroll 2
        for (int kk = 0; kk < 256; kk += 16) {
            uint32_t ah[4], al[4], tb[4];
            uint32_t bh0[2], bh1[2], bl0[2], bl1[2];
            ldsm4(ah, rAh + kk * 2);
            ldsm4(al, rAl + kk * 2);
            ldsm4(tb, rBh + kk * 2);
            bh0[0] = tb[0]; bh1[0] = tb[1]; bh0[1] = tb[2]; bh1[1] = tb[3];
            ldsm4(tb, rBl + kk * 2);
            bl0[0] = tb[0]; bl1[0] = tb[1]; bl0[1] = tb[2]; bl1[1] = tb[3];
            mma_bf16(acc[0], ah, bh0);
            mma_bf16(acc[0], ah, bl0);
            mma_bf16(acc[0], al, bh0);
            mma_bf16(acc[1], ah, bh1);
            mma_bf16(acc[1], ah, bl1);
            mma_bf16(acc[1], al, bh1);
        }
        {
            float* Gk = Gs + kh * (32 * 65);
#pragma unroll
            for (int nf = 0; nf < 2; nf++) {
                int r = m_off + lr, c = n_off + nf * 8 + lc;
                Gk[r * 65 + c] = acc[nf][0];
                Gk[r * 65 + c + 1] = acc[nf][1];
                Gk[(r + 8) * 65 + c] = acc[nf][2];
                Gk[(r + 8) * 65 + c + 1] = acc[nf][3];
            }
        }
        __syncthreads();

        __nv_bfloat16* hnh = (t & 1) ? g_hpA : g_hpB;
        __nv_bfloat16* hnl = (t & 1) ? g_lpA : g_lpB;
        {
            float iv = Gs[rr * 65 + jj] + Gs[32 * 65 + rr * 65 + jj] + x0;
            float fv = Gs[rr * 65 + 16 + jj] + Gs[32 * 65 + rr * 65 + 16 + jj] + x1;
            float cv = Gs[rr * 65 + 32 + jj] + Gs[32 * 65 + rr * 65 + 32 + jj] + x2;
            float ov = Gs[rr * 65 + 48 + jj] + Gs[32 * 65 + rr * 65 + 48 + jj] + x3;
            iv = fsigm(iv);
            fv = fsigm(fv);
            ov = fsigm(ov);
            cv = ftanh(cv);
            float c = fv * creg + iv * cv;
            creg = c;
            float h = ov * ftanh(c);
            __nv_bfloat16 vh, vl;
            bsplit(h, &vh, &vl);
            hnh[(size_t)(b0 + rr) * HH + j0 + jj] = vh;
            hnl[(size_t)(b0 + rr) * HH + j0 + jj] = vl;
            if (layer == 0) {
                g_sh[((size_t)(b0 + rr) * TT + t) * HH + j0 + jj] = vh;
                g_sl[((size_t)(b0 + rr) * TT + t) * HH + j0 + jj] = vl;
            } else if (t == TT - 1) {
                g_hfin[(size_t)(b0 + rr) * HH + j0 + jj] = h;
            }
        }

        if (t < TT - 1) {
            // prefetch next step's xg BEFORE the barrier (rides through the spin)
            const float* xb = g_xg + ((size_t)(b0 + rr) * TT + (t + 1)) * G4 + j0 + jj;
            x0 = xb[0]; x1 = xb[512]; x2 = xb[1024]; x3 = xb[1536];
            grid_bar4(grp);
        }
    }
}

// ---------------- layernorm (eps=1e-3) on g_hfin ----------------
__global__ void layernorm(const float* __restrict__ gamma, const float* __restrict__ beta) {
    const int b = blockIdx.x, tid = threadIdx.x;
    const float* __restrict__ h = &g_hfin[b * HH];
    __shared__ float red[8];
    __shared__ float bc_mu, bc_rs;
    float s = 0.f;
    for (int j = tid; j < HH; j += 256) s += h[j];
#pragma unroll
    for (int o = 16; o; o >>= 1) s += __shfl_xor_sync(0xffffffffu, s, o);
    if ((tid & 31) == 0) red[tid >> 5] = s;
    __syncthreads();
    if (tid == 0) {
        float ts = 0.f;
        for (int i = 0; i < 8; i++) ts += red[i];
        bc_mu = ts / (float)HH;
    }
    __syncthreads();
    float mu = bc_mu;
    float v = 0.f;
    for (int j = tid; j < HH; j += 256) { float dd = h[j] - mu; v += dd * dd; }
#pragma unroll
    for (int o = 16; o; o >>= 1) v += __shfl_xor_sync(0xffffffffu, v, o);
    __syncthreads();
    if ((tid & 31) == 0) red[tid >> 5] = v;
    __syncthreads();
    if (tid == 0) {
        float ts = 0.f;
        for (int i = 0; i < 8; i++) ts += red[i];
        bc_rs = rsqrtf(ts / (float)HH + 1e-3f);
    }
    __syncthreads();
    float rs = bc_rs;
    for (int j = tid; j < HH; j += 256)
        g_ln[b * HH + j] = (h[j] - mu) * rs * gamma[j] + beta[j];
}

// ---------------- dense2 + relu ----------------
__global__ void dense2(const float* __restrict__ W2, const float* __restrict__ b2) {
    const int b = blockIdx.x, c = threadIdx.x;
    const float* __restrict__ h = &g_ln[b * HH];
    float s = b2[c];
    for (int k = 0; k < HH; k++) s += h[k] * W2[k * 256 + c];
    g_d2[b * 256 + c] = fmaxf(s, 0.f);
}

// ---------------- dense3 ----------------
__global__ void dense3(const float* __restrict__ W3, const float* __restrict__ b3,
                       float* __restrict__ out) {
    const int b = blockIdx.x, tid = threadIdx.x;
    float s = g_d2[b * 256 + tid] * W3[tid];
#pragma unroll
    for (int o = 16; o; o >>= 1) s += __shfl_xor_sync(0xffffffffu, s, o);
    __shared__ float red[8];
    if ((tid & 31) == 0) red[tid >> 5] = s;
    __syncthreads();
    if (tid == 0) {
        float ts = 0.f;
        for (int i = 0; i < 8; i++) ts += red[i];
        out[b] = ts + b3[0];
    }
}

// ---------------- launch ----------------
extern "C" void kernel_launch(void* const* d_in, const int* in_sizes, int n_in,
                              void* d_out, int out_size) {
    const float* x     = (const float*)d_in[0];
    const float* W1    = (const float*)d_in[1];
    const float* b1    = (const float*)d_in[2];
    const float* Wx1   = (const float*)d_in[3];
    const float* Wh1   = (const float*)d_in[4];
    const float* bl1   = (const float*)d_in[5];
    const float* Wx2   = (const float*)d_in[6];
    const float* Wh2   = (const float*)d_in[7];
    const float* bl2   = (const float*)d_in[8];
    const float* gamma = (const float*)d_in[9];
    const float* beta  = (const float*)d_in[10];
    const float* W2    = (const float*)d_in[11];
    const float* b2    = (const float*)d_in[12];
    const float* W3    = (const float*)d_in[13];
    const float* b3    = (const float*)d_in[14];
    float* out = (float*)d_out;

    static int init_done = 0;
    if (!init_done) {
        cudaFuncSetAttribute(lstm_mma, cudaFuncAttributeMaxDynamicSharedMemorySize,
                             L_SMEM);
        cudaFuncSetAttribute(gemm_xg, cudaFuncAttributeMaxDynamicSharedMemorySize,
                             XS_SMEM);
        init_done = 1;
    }

    dense1_norm<<<(BB * TT) / 16, 256>>>(x, W1, b1);
    convW<<<dim3(G4 / 32, HH / 32), 256>>>(Wx1, 0);
    convW<<<dim3(G4 / 32, HH / 32), 256>>>(Wx2, 1);

    gemm_xg<<<dim3(G4 / 128, (BB * TT) / 128), 256, XS_SMEM>>>(0, bl1);
    zero_h<<<(BB * HH / 2 + 255) / 256, 256>>>();
    lstm_mma<<<NBLK, 512, L_SMEM>>>(Wh1, 0);

    gemm_xg<<<dim3(G4 / 128, (BB * TT) / 128), 256, XS_SMEM>>>(1, bl2);
    zero_h<<<(BB * HH / 2 + 255) / 256, 256>>>();
    lstm_mma<<<NBLK, 512, L_SMEM>>>(Wh2, 1);

    layernorm<<<BB, 256>>>(gamma, beta);
    dense2<<<BB, 256>>>(W2, b2);
    dense3<<<BB, 256>>>(W3, b3, out);
}

// round 14
// speedup vs baseline: 1.0402x; 1.0402x over previous
#include <cuda_runtime.h>
#include <cuda_bf16.h>
#include <math.h>
#include <stdint.h>

#define BB 128
#define TT 256
#define FF 64
#define HH 512
#define G4 2048
#define NBLK 128  // persistent LSTM grid

// ---------------- mma / ldmatrix / cp.async helpers (arch-generic) ----------
__device__ __forceinline__ void mma_bf16(float* d, const uint32_t* a, const uint32_t* b) {
    asm volatile(
        "mma.sync.aligned.m16n8k16.row.col.f32.bf16.bf16.f32 "
        "{%0,%1,%2,%3}, {%4,%5,%6,%7}, {%8,%9}, {%0,%1,%2,%3};"
        : "+f"(d[0]), "+f"(d[1]), "+f"(d[2]), "+f"(d[3])
        : "r"(a[0]), "r"(a[1]), "r"(a[2]), "r"(a[3]), "r"(b[0]), "r"(b[1]));
}
__device__ __forceinline__ void ldsm4(uint32_t* r, uint32_t addr) {
    asm volatile("ldmatrix.sync.aligned.m8n8.x4.shared.b16 {%0,%1,%2,%3}, [%4];"
        : "=r"(r[0]), "=r"(r[1]), "=r"(r[2]), "=r"(r[3]) : "r"(addr));
}
__device__ __forceinline__ uint32_t smem_u32(const void* p) {
    uint32_t a;
    asm("{ .reg .u64 t; cvta.to.shared.u64 t, %1; cvt.u32.u64 %0, t; }"
        : "=r"(a) : "l"(p));
    return a;
}
__device__ __forceinline__ void cp16(uint32_t dst, const void* src) {
    asm volatile("cp.async.cg.shared.global [%0], [%1], 16;"
        :: "r"(dst), "l"(src) : "memory");
}
#define CP_COMMIT() asm volatile("cp.async.commit_group;" ::: "memory")
#define CP_WAIT0()  asm volatile("cp.async.wait_group 0;" ::: "memory")

__device__ __forceinline__ void bsplit(float w, __nv_bfloat16* hi, __nv_bfloat16* lo) {
    __nv_bfloat16 h = __float2bfloat16(w);
    *hi = h;
    *lo = __float2bfloat16(w - __bfloat162float(h));
}
__device__ __forceinline__ float fsigm(float x) {
    return __fdividef(1.f, 1.f + __expf(-x));
}
__device__ __forceinline__ float ftanh(float x) {
    x = fminf(fmaxf(x, -15.f), 15.f);
    float e = __expf(-2.f * x);
    return __fdividef(1.f - e, 1.f + e);
}

// ---------------- scratch ----------------
__device__ __nv_bfloat16 g_hh[BB * TT * HH], g_hl[BB * TT * HH];
__device__ __nv_bfloat16 g_sh[BB * TT * HH], g_sl[BB * TT * HH];
__device__ __nv_bfloat16 g_Wxh[2][G4 * HH], g_Wxl[2][G4 * HH];
__device__ float g_xg[(size_t)BB * TT * G4];
__device__ __nv_bfloat16 g_hpA[BB * HH], g_hpB[BB * HH];
__device__ __nv_bfloat16 g_lpA[BB * HH], g_lpB[BB * HH];
__device__ float g_hfin[BB * HH];
__device__ float g_ln[BB * HH];
__device__ float g_d2[BB * (HH / 2)];
__device__ unsigned g_cnt4[4];
__device__ unsigned g_gen4[4];

// ------- per-batch-group grid barrier: release-arrive / acquire-spin --------
__device__ __forceinline__ void grid_bar4(int grp) {
    __syncthreads();
    if (threadIdx.x == 0) {
        unsigned* cp = &g_cnt4[grp];
        unsigned* gp = &g_gen4[grp];
        unsigned gen;
        asm volatile("ld.acquire.gpu.u32 %0, [%1];" : "=r"(gen) : "l"(gp));
        unsigned old;
        asm volatile("atom.add.release.gpu.u32 %0, [%1], 1;" : "=r"(old) : "l"(cp) : "memory");
        if (old == 31u) {
            asm volatile("st.relaxed.gpu.u32 [%0], 0;" :: "l"(cp) : "memory");
            asm volatile("red.add.release.gpu.u32 [%0], 1;" :: "l"(gp) : "memory");
        } else {
            unsigned g2;
            do {
                asm volatile("ld.acquire.gpu.u32 %0, [%1];" : "=r"(g2) : "l"(gp));
            } while (g2 == gen);
        }
    }
    __syncthreads();
}

// ---------------- dense1 + L2-norm scale (writes bf16 splits) ---------------
__global__ void dense1_norm(const float* __restrict__ x, const float* __restrict__ W1,
                            const float* __restrict__ b1) {
    __shared__ float xs[16][FF];
    __shared__ float hs[16][HH];
    const int tid = threadIdx.x;
    const int m0 = blockIdx.x * 16;
    for (int i = tid; i < 16 * FF; i += 256)
        xs[i / FF][i % FF] = x[(m0 + i / FF) * FF + i % FF];
    __syncthreads();
    const int c0 = tid * 2;
    float a0[16], a1[16];
#pragma unroll
    for (int r = 0; r < 16; r++) { a0[r] = 0.f; a1[r] = 0.f; }
    for (int k = 0; k < FF; k++) {
        float w0 = W1[k * HH + c0], w1 = W1[k * HH + c0 + 1];
#pragma unroll
        for (int r = 0; r < 16; r++) { float xv = xs[r][k]; a0[r] += xv * w0; a1[r] += xv * w1; }
    }
    float bb0 = b1[c0], bb1 = b1[c0 + 1];
#pragma unroll
    for (int r = 0; r < 16; r++) { hs[r][c0] = a0[r] + bb0; hs[r][c0 + 1] = a1[r] + bb1; }
    __syncthreads();
    int wid = tid >> 5, lane = tid & 31;
#pragma unroll
    for (int rr = 0; rr < 2; rr++) {
        int r = wid * 2 + rr;
        float ss = 0.f;
        for (int c = lane; c < HH; c += 32) { float v = hs[r][c]; ss += v * v; }
#pragma unroll
        for (int o = 16; o; o >>= 1) ss += __shfl_xor_sync(0xffffffffu, ss, o);
        float sc = sqrtf((float)HH) / fmaxf(sqrtf(ss), 1e-12f);
        for (int c = lane; c < HH; c += 32) {
            float v = hs[r][c] * sc;
            __nv_bfloat16 vh, vl;
            bsplit(v, &vh, &vl);
            g_hh[(size_t)(m0 + r) * HH + c] = vh;
            g_hl[(size_t)(m0 + r) * HH + c] = vl;
        }
    }
}

// ---------------- Wx -> transposed bf16 splits [n][k], tiled ----------------
__global__ void convW(const float* __restrict__ W, int layer) {
    __shared__ float tile[32][33];
    const int tx = threadIdx.x & 31, ty4 = (threadIdx.x >> 5) * 4;
    const int n0 = blockIdx.x * 32, k0 = blockIdx.y * 32;
#pragma unroll
    for (int r = 0; r < 4; r++)
        tile[ty4 + r][tx] = W[(size_t)(k0 + ty4 + r) * G4 + n0 + tx];
    __syncthreads();
#pragma unroll
    for (int r = 0; r < 4; r++) {
        int n = n0 + ty4 + r;
        float w = tile[tx][ty4 + r];
        __nv_bfloat16 h_, l_;
        bsplit(w, &h_, &l_);
        g_Wxh[layer][(size_t)n * HH + k0 + tx] = h_;
        g_Wxl[layer][(size_t)n * HH + k0 + tx] = l_;
    }
}

// ---------------- xg GEMM: 256 thr, 8 warps (4m x 2n), warp 32x64, Kc=32 ----
// single __syncthreads per chunk: wait -> sync -> issue next -> compute
#define XS_ROW   80                    // 32 bf16 (64B) + 16B pad
#define XS_ARR   (128 * XS_ROW)        // 10240
#define XS_STAGE (4 * XS_ARR)          // 40960
#define XS_SMEM  (2 * XS_STAGE)        // 81920

__global__ void __launch_bounds__(256, 2) gemm_xg(int layer, const float* __restrict__ bias) {
    const __nv_bfloat16* __restrict__ Ah = layer ? g_sh : g_hh;
    const __nv_bfloat16* __restrict__ Al = layer ? g_sl : g_hl;
    const __nv_bfloat16* __restrict__ Bh = g_Wxh[layer];
    const __nv_bfloat16* __restrict__ Bl = g_Wxl[layer];

    extern __shared__ __align__(16) uint8_t smd[];
    const int tid = threadIdx.x;
    const int lane = tid & 31, wid = tid >> 5;
    const int n0 = blockIdx.x * 128, m0 = blockIdx.y * 128;
    const int m_off = (wid >> 1) * 32, n_off = (wid & 1) * 64;
    const int lr = lane >> 2, lc = (lane & 3) * 2;

    float acc[2][8][4];
#pragma unroll
    for (int i = 0; i < 2; i++)
#pragma unroll
        for (int j = 0; j < 8; j++)
#pragma unroll
            for (int q = 0; q < 4; q++) acc[i][j][q] = 0.f;

    const uint32_t smb = smem_u32(smd);
    const __nv_bfloat16* srcs[8];
    uint32_t dsts[8];
#pragma unroll
    for (int j = 0; j < 8; j++) {
        int id = tid + 256 * j;
        int arr = id >> 9, row = (id >> 2) & 127, seg = id & 3;
        const __nv_bfloat16* base =
            (arr == 0 ? Ah + (size_t)(m0 + row) * HH :
             arr == 1 ? Al + (size_t)(m0 + row) * HH :
             arr == 2 ? Bh + (size_t)(n0 + row) * HH :
                        Bl + (size_t)(n0 + row) * HH);
        srcs[j] = base + seg * 8;
        dsts[j] = smb + arr * XS_ARR + row * XS_ROW + seg * 16;
    }

#pragma unroll
    for (int j = 0; j < 8; j++) cp16(dsts[j], srcs[j]);
    CP_COMMIT();

    int s = 0;
    for (int kc = 0; kc < HH; kc += 32) {
        CP_WAIT0();
        __syncthreads();
        if (kc + 32 < HH) {
#pragma unroll
            for (int j = 0; j < 8; j++) cp16(dsts[j] + (s ^ 1) * XS_STAGE, srcs[j] + kc + 32);
            CP_COMMIT();
        }
        const uint32_t sb = smb + s * XS_STAGE;

#pragma unroll
        for (int ks = 0; ks < 32; ks += 16) {
            uint32_t afh[2][4], afl[2][4];
#pragma unroll
            for (int mi = 0; mi < 2; mi++) {
                uint32_t ar = sb + (m_off + mi * 16 + (lane & 15)) * XS_ROW +
                              ks * 2 + (lane >> 4) * 16;
                ldsm4(afh[mi], ar);
                ldsm4(afl[mi], ar + XS_ARR);
            }
            uint32_t bfh[8][2], bfl[8][2];
#pragma unroll
            for (int g = 0; g < 4; g++) {
                uint32_t br = sb + 2 * XS_ARR + (n_off + g * 16 + (lane & 15)) * XS_ROW +
                              ks * 2 + (lane >> 4) * 16;
                uint32_t tt[4];
                ldsm4(tt, br);
                bfh[2 * g][0] = tt[0]; bfh[2 * g + 1][0] = tt[1];
                bfh[2 * g][1] = tt[2]; bfh[2 * g + 1][1] = tt[3];
                ldsm4(tt, br + XS_ARR);
                bfl[2 * g][0] = tt[0]; bfl[2 * g + 1][0] = tt[1];
                bfl[2 * g][1] = tt[2]; bfl[2 * g + 1][1] = tt[3];
            }
#pragma unroll
            for (int mi = 0; mi < 2; mi++)
#pragma unroll
                for (int nf = 0; nf < 8; nf++) {
                    mma_bf16(acc[mi][nf], afh[mi], bfh[nf]);
                    mma_bf16(acc[mi][nf], afh[mi], bfl[nf]);
                    mma_bf16(acc[mi][nf], afl[mi], bfh[nf]);
                }
        }
        s ^= 1;
    }

#pragma unroll
    for (int mi = 0; mi < 2; mi++)
#pragma unroll
        for (int nf = 0; nf < 8; nf++) {
            int r = m0 + m_off + mi * 16 + lr;
            int c = n0 + n_off + nf * 8 + lc;
            float2 bv = *(const float2*)&bias[c];
            *(float2*)&g_xg[(size_t)r * G4 + c] =
                make_float2(acc[mi][nf][0] + bv.x, acc[mi][nf][1] + bv.y);
            *(float2*)&g_xg[(size_t)(r + 8) * G4 + c] =
                make_float2(acc[mi][nf][2] + bv.x, acc[mi][nf][3] + bv.y);
        }
}

// ---------------- zero initial h splits ----------------
__global__ void zero_h() {
    int i = blockIdx.x * 256 + threadIdx.x;
    if (i < BB * HH / 2) {
        ((unsigned*)g_hpA)[i] = 0u;
        ((unsigned*)g_lpA)[i] = 0u;
    }
}

// ==================== persistent mma.sync LSTM (512 thr, K-split) ===========
// 128 blocks; block = 32 batch x 64 gate-cols. Warps 0-7: K[0,256), 8-15: K[256,512).
// Exact round-11 structure (xg prefetch at loop top, after the barrier).
#define L_BHI 0
#define L_BLO 66560
#define L_AHI 133120
#define L_ALO 166400
#define L_GS  199680
#define L_SMEM 216320

__global__ void __launch_bounds__(512, 1)
lstm_mma(const float* __restrict__ Wh, int layer) {
    extern __shared__ __align__(16) uint8_t sm[];
    const int tid = threadIdx.x, lane = tid & 31, wid = tid >> 5;
    const int grp = blockIdx.x >> 5;
    const int b0 = grp * 32;
    const int j0 = (blockIdx.x & 31) * 16;
    const int kh = wid >> 3;
    const int wq = wid & 7;
    const int m_off = (wq >> 2) * 16, n_off = (wq & 3) * 16;
    const int lr = lane >> 2, lc = (lane & 3) * 2;

    for (int i = tid; i < 64 * HH; i += 512) {
        int n = i & 63, k = i >> 6;
        float w = Wh[k * G4 + (n >> 4) * HH + j0 + (n & 15)];
        __nv_bfloat16 h_, l_;
        bsplit(w, &h_, &l_);
        *(__nv_bfloat16*)(sm + L_BHI + ((size_t)n * 520 + k) * 2) = h_;
        *(__nv_bfloat16*)(sm + L_BLO + ((size_t)n * 520 + k) * 2) = l_;
    }
    __syncthreads();

    float* Gs = (float*)(sm + L_GS);
    const uint32_t smb = smem_u32(sm);
    const int rr = tid >> 4, jj = tid & 15;
    const int tidl = tid & 255;
    const int kbase = kh * 256;
    float creg = 0.f;

    const uint32_t rAh = smb + L_AHI + (m_off + (lane & 15)) * 1040 + (lane >> 4) * 16 + kh * 512;
    const uint32_t rAl = smb + L_ALO + (m_off + (lane & 15)) * 1040 + (lane >> 4) * 16 + kh * 512;
    const uint32_t rBh = smb + L_BHI + (n_off + (lane & 15)) * 1040 + (lane >> 4) * 16 + kh * 512;
    const uint32_t rBl = smb + L_BLO + (n_off + (lane & 15)) * 1040 + (lane >> 4) * 16 + kh * 512;

    for (int t = 0; t < TT; t++) {
        const __nv_bfloat16* hph = (t & 1) ? g_hpB : g_hpA;
        const __nv_bfloat16* hpl = (t & 1) ? g_lpB : g_lpA;

        // xg prefetch (overlaps with the cp.async phase below)
        const float* xb = g_xg + ((size_t)(b0 + rr) * TT + t) * G4 + j0 + jj;
        float x0 = xb[0], x1 = xb[512], x2 = xb[1024], x3 = xb[1536];

        // each K-half warp-group loads ONLY its own half of the h tile
#pragma unroll
        for (int idx = tidl; idx < 1024; idx += 256) {
            int row = idx >> 5, k8 = (idx & 31) * 8 + kbase;
            cp16(smb + L_AHI + row * 1040 + k8 * 2, hph + (size_t)(b0 + row) * HH + k8);
            cp16(smb + L_ALO + row * 1040 + k8 * 2, hpl + (size_t)(b0 + row) * HH + k8);
        }
        CP_COMMIT();
        CP_WAIT0();
        asm volatile("bar.sync %0, 256;" :: "r"(4 + kh) : "memory");

        float acc[2][4] = {{0.f, 0.f, 0.f, 0.f}, {0.f, 0.f, 0.f, 0.f}};
#pragma unroll 2
        for (int kk = 0; kk < 256; kk += 16) {
            uint32_t ah[4], al[4], tb[4];
            uint32_t bh0[2], bh1[2], bl0[2], bl1[2];
            ldsm4(ah, rAh + kk * 2);
            ldsm4(al, rAl + kk * 2);
            ldsm4(tb, rBh + kk * 2);
            bh0[0] = tb[0]; bh1[0] = tb[1]; bh0[1] = tb[2]; bh1[1] = tb[3];
            ldsm4(tb, rBl + kk * 2);
            bl0[0] = tb[0]; bl1[0] = tb[1]; bl0[1] = tb[2]; bl1[1] = tb[3];
            mma_bf16(acc[0], ah, bh0);
            mma_bf16(acc[0], ah, bl0);
            mma_bf16(acc[0], al, bh0);
            mma_bf16(acc[1], ah, bh1);
            mma_bf16(acc[1], ah, bl1);
            mma_bf16(acc[1], al, bh1);
        }
        {
            float* Gk = Gs + kh * (32 * 65);
#pragma unroll
            for (int nf = 0; nf < 2; nf++) {
                int r = m_off + lr, c = n_off + nf * 8 + lc;
                Gk[r * 65 + c] = acc[nf][0];
                Gk[r * 65 + c + 1] = acc[nf][1];
                Gk[(r + 8) * 65 + c] = acc[nf][2];
                Gk[(r + 8) * 65 + c + 1] = acc[nf][3];
            }
        }
        __syncthreads();

        __nv_bfloat16* hnh = (t & 1) ? g_hpA : g_hpB;
        __nv_bfloat16* hnl = (t & 1) ? g_lpA : g_lpB;
        {
            float iv = Gs[rr * 65 + jj] + Gs[32 * 65 + rr * 65 + jj] + x0;
            float fv = Gs[rr * 65 + 16 + jj] + Gs[32 * 65 + rr * 65 + 16 + jj] + x1;
            float cv = Gs[rr * 65 + 32 + jj] + Gs[32 * 65 + rr * 65 + 32 + jj] + x2;
            float ov = Gs[rr * 65 + 48 + jj] + Gs[32 * 65 + rr * 65 + 48 + jj] + x3;
            iv = fsigm(iv);
            fv = fsigm(fv);
            ov = fsigm(ov);
            cv = ftanh(cv);
            float c = fv * creg + iv * cv;
            creg = c;
            float h = ov * ftanh(c);
            __nv_bfloat16 vh, vl;
            bsplit(h, &vh, &vl);
            hnh[(size_t)(b0 + rr) * HH + j0 + jj] = vh;
            hnl[(size_t)(b0 + rr) * HH + j0 + jj] = vl;
            if (layer == 0) {
                g_sh[((size_t)(b0 + rr) * TT + t) * HH + j0 + jj] = vh;
                g_sl[((size_t)(b0 + rr) * TT + t) * HH + j0 + jj] = vl;
            } else if (t == TT - 1) {
                g_hfin[(size_t)(b0 + rr) * HH + j0 + jj] = h;
            }
        }
        if (t < TT - 1) grid_bar4(grp);
    }
}

// ---------------- layernorm (eps=1e-3) on g_hfin ----------------
__global__ void layernorm(const float* __restrict__ gamma, const float* __restrict__ beta) {
    const int b = blockIdx.x, tid = threadIdx.x;
    const float* __restrict__ h = &g_hfin[b * HH];
    __shared__ float red[8];
    __shared__ float bc_mu, bc_rs;
    float s = 0.f;
    for (int j = tid; j < HH; j += 256) s += h[j];
#pragma unroll
    for (int o = 16; o; o >>= 1) s += __shfl_xor_sync(0xffffffffu, s, o);
    if ((tid & 31) == 0) red[tid >> 5] = s;
    __syncthreads();
    if (tid == 0) {
        float ts = 0.f;
        for (int i = 0; i < 8; i++) ts += red[i];
        bc_mu = ts / (float)HH;
    }
    __syncthreads();
    float mu = bc_mu;
    float v = 0.f;
    for (int j = tid; j < HH; j += 256) { float dd = h[j] - mu; v += dd * dd; }
#pragma unroll
    for (int o = 16; o; o >>= 1) v += __shfl_xor_sync(0xffffffffu, v, o);
    __syncthreads();
    if ((tid & 31) == 0) red[tid >> 5] = v;
    __syncthreads();
    if (tid == 0) {
        float ts = 0.f;
        for (int i = 0; i < 8; i++) ts += red[i];
        bc_rs = rsqrtf(ts / (float)HH + 1e-3f);
    }
    __syncthreads();
    float rs = bc_rs;
    for (int j = tid; j < HH; j += 256)
        g_ln[b * HH + j] = (h[j] - mu) * rs * gamma[j] + beta[j];
}

// ---------------- dense2 + relu ----------------
__global__ void dense2(const float* __restrict__ W2, const float* __restrict__ b2) {
    const int b = blockIdx.x, c = threadIdx.x;
    const float* __restrict__ h = &g_ln[b * HH];
    float s = b2[c];
    for (int k = 0; k < HH; k++) s += h[k] * W2[k * 256 + c];
    g_d2[b * 256 + c] = fmaxf(s, 0.f);
}

// ---------------- dense3 ----------------
__global__ void dense3(const float* __restrict__ W3, const float* __restrict__ b3,
                       float* __restrict__ out) {
    const int b = blockIdx.x, tid = threadIdx.x;
    float s = g_d2[b * 256 + tid] * W3[tid];
#pragma unroll
    for (int o = 16; o; o >>= 1) s += __shfl_xor_sync(0xffffffffu, s, o);
    __shared__ float red[8];
    if ((tid & 31) == 0) red[tid >> 5] = s;
    __syncthreads();
    if (tid == 0) {
        float ts = 0.f;
        for (int i = 0; i < 8; i++) ts += red[i];
        out[b] = ts + b3[0];
    }
}

// ---------------- launch ----------------
extern "C" void kernel_launch(void* const* d_in, const int* in_sizes, int n_in,
                              void* d_out, int out_size) {
    const float* x     = (const float*)d_in[0];
    const float* W1    = (const float*)d_in[1];
    const float* b1    = (const float*)d_in[2];
    const float* Wx1   = (const float*)d_in[3];
    const float* Wh1   = (const float*)d_in[4];
    const float* bl1   = (const float*)d_in[5];
    const float* Wx2   = (const float*)d_in[6];
    const float* Wh2   = (const float*)d_in[7];
    const float* bl2   = (const float*)d_in[8];
    const float* gamma = (const float*)d_in[9];
    const float* beta  = (const float*)d_in[10];
    const float* W2    = (const float*)d_in[11];
    const float* b2    = (const float*)d_in[12];
    const float* W3    = (const float*)d_in[13];
    const float* b3    = (const float*)d_in[14];
    float* out = (float*)d_out;

    static int init_done = 0;
    if (!init_done) {
        cudaFuncSetAttribute(lstm_mma, cudaFuncAttributeMaxDynamicSharedMemorySize,
                             L_SMEM);
        cudaFuncSetAttribute(gemm_xg, cudaFuncAttributeMaxDynamicSharedMemorySize,
                             XS_SMEM);
        init_done = 1;
    }

    dense1_norm<<<(BB * TT) / 16, 256>>>(x, W1, b1);
    convW<<<dim3(G4 / 32, HH / 32), 256>>>(Wx1, 0);
    convW<<<dim3(G4 / 32, HH / 32), 256>>>(Wx2, 1);

    gemm_xg<<<dim3(G4 / 128, (BB * TT) / 128), 256, XS_SMEM>>>(0, bl1);
    zero_h<<<(BB * HH / 2 + 255) / 256, 256>>>();
    lstm_mma<<<NBLK, 512, L_SMEM>>>(Wh1, 0);

    gemm_xg<<<dim3(G4 / 128, (BB * TT) / 128), 256, XS_SMEM>>>(1, bl2);
    zero_h<<<(BB * HH / 2 + 255) / 256, 256>>>();
    lstm_mma<<<NBLK, 512, L_SMEM>>>(Wh2, 1);

    layernorm<<<BB, 256>>>(gamma, beta);
    dense2<<<BB, 256>>>(W2, b2);
    dense3<<<BB, 256>>>(W3, b3, out);
}

// round 15
// speedup vs baseline: 1.0715x; 1.0300x over previous
#include <cuda_runtime.h>
#include <cuda_bf16.h>
#include <math.h>
#include <stdint.h>

#define BB 128
#define TT 256
#define FF 64
#define HH 512
#define G4 2048
#define NBLK 128  // persistent LSTM grid

// ---------------- mma / ldmatrix / cp.async helpers (arch-generic) ----------
__device__ __forceinline__ void mma_bf16(float* d, const uint32_t* a, const uint32_t* b) {
    asm volatile(
        "mma.sync.aligned.m16n8k16.row.col.f32.bf16.bf16.f32 "
        "{%0,%1,%2,%3}, {%4,%5,%6,%7}, {%8,%9}, {%0,%1,%2,%3};"
        : "+f"(d[0]), "+f"(d[1]), "+f"(d[2]), "+f"(d[3])
        : "r"(a[0]), "r"(a[1]), "r"(a[2]), "r"(a[3]), "r"(b[0]), "r"(b[1]));
}
__device__ __forceinline__ void ldsm4(uint32_t* r, uint32_t addr) {
    asm volatile("ldmatrix.sync.aligned.m8n8.x4.shared.b16 {%0,%1,%2,%3}, [%4];"
        : "=r"(r[0]), "=r"(r[1]), "=r"(r[2]), "=r"(r[3]) : "r"(addr));
}
__device__ __forceinline__ uint32_t smem_u32(const void* p) {
    uint32_t a;
    asm("{ .reg .u64 t; cvta.to.shared.u64 t, %1; cvt.u32.u64 %0, t; }"
        : "=r"(a) : "l"(p));
    return a;
}
__device__ __forceinline__ void cp16(uint32_t dst, const void* src) {
    asm volatile("cp.async.cg.shared.global [%0], [%1], 16;"
        :: "r"(dst), "l"(src) : "memory");
}
#define CP_COMMIT() asm volatile("cp.async.commit_group;" ::: "memory")
#define CP_WAIT0()  asm volatile("cp.async.wait_group 0;" ::: "memory")
#define CP_WAIT1()  asm volatile("cp.async.wait_group 1;" ::: "memory")

__device__ __forceinline__ void bsplit(float w, __nv_bfloat16* hi, __nv_bfloat16* lo) {
    __nv_bfloat16 h = __float2bfloat16(w);
    *hi = h;
    *lo = __float2bfloat16(w - __bfloat162float(h));
}
__device__ __forceinline__ float fsigm(float x) {
    return __fdividef(1.f, 1.f + __expf(-x));
}
__device__ __forceinline__ float ftanh(float x) {
    x = fminf(fmaxf(x, -15.f), 15.f);
    float e = __expf(-2.f * x);
    return __fdividef(1.f - e, 1.f + e);
}

// ---------------- scratch ----------------
__device__ __nv_bfloat16 g_hh[BB * TT * HH], g_hl[BB * TT * HH];
__device__ __nv_bfloat16 g_sh[BB * TT * HH], g_sl[BB * TT * HH];
__device__ __nv_bfloat16 g_Wxh[2][G4 * HH], g_Wxl[2][G4 * HH];
__device__ float g_xg[(size_t)BB * TT * G4];
__device__ __nv_bfloat16 g_hpA[BB * HH], g_hpB[BB * HH];
__device__ __nv_bfloat16 g_lpA[BB * HH], g_lpB[BB * HH];
__device__ float g_hfin[BB * HH];
__device__ float g_ln[BB * HH];
__device__ float g_d2[BB * (HH / 2)];
__device__ unsigned g_cnt4[4];
__device__ unsigned g_gen4[4];

// ------- per-batch-group grid barrier: release-arrive / acquire-spin --------
__device__ __forceinline__ void grid_bar4(int grp) {
    __syncthreads();
    if (threadIdx.x == 0) {
        unsigned* cp = &g_cnt4[grp];
        unsigned* gp = &g_gen4[grp];
        unsigned gen;
        asm volatile("ld.acquire.gpu.u32 %0, [%1];" : "=r"(gen) : "l"(gp));
        unsigned old;
        asm volatile("atom.add.release.gpu.u32 %0, [%1], 1;" : "=r"(old) : "l"(cp) : "memory");
        if (old == 31u) {
            asm volatile("st.relaxed.gpu.u32 [%0], 0;" :: "l"(cp) : "memory");
            asm volatile("red.add.release.gpu.u32 [%0], 1;" :: "l"(gp) : "memory");
        } else {
            unsigned g2;
            do {
                asm volatile("ld.acquire.gpu.u32 %0, [%1];" : "=r"(g2) : "l"(gp));
            } while (g2 == gen);
        }
    }
    __syncthreads();
}

// ---------------- dense1 + L2-norm scale (writes bf16 splits) ---------------
__global__ void dense1_norm(const float* __restrict__ x, const float* __restrict__ W1,
                            const float* __restrict__ b1) {
    __shared__ float xs[16][FF];
    __shared__ float hs[16][HH];
    const int tid = threadIdx.x;
    const int m0 = blockIdx.x * 16;
    for (int i = tid; i < 16 * FF; i += 256)
        xs[i / FF][i % FF] = x[(m0 + i / FF) * FF + i % FF];
    __syncthreads();
    const int c0 = tid * 2;
    float a0[16], a1[16];
#pragma unroll
    for (int r = 0; r < 16; r++) { a0[r] = 0.f; a1[r] = 0.f; }
    for (int k = 0; k < FF; k++) {
        float w0 = W1[k * HH + c0], w1 = W1[k * HH + c0 + 1];
#pragma unroll
        for (int r = 0; r < 16; r++) { float xv = xs[r][k]; a0[r] += xv * w0; a1[r] += xv * w1; }
    }
    float bb0 = b1[c0], bb1 = b1[c0 + 1];
#pragma unroll
    for (int r = 0; r < 16; r++) { hs[r][c0] = a0[r] + bb0; hs[r][c0 + 1] = a1[r] + bb1; }
    __syncthreads();
    int wid = tid >> 5, lane = tid & 31;
#pragma unroll
    for (int rr = 0; rr < 2; rr++) {
        int r = wid * 2 + rr;
        float ss = 0.f;
        for (int c = lane; c < HH; c += 32) { float v = hs[r][c]; ss += v * v; }
#pragma unroll
        for (int o = 16; o; o >>= 1) ss += __shfl_xor_sync(0xffffffffu, ss, o);
        float sc = sqrtf((float)HH) / fmaxf(sqrtf(ss), 1e-12f);
        for (int c = lane; c < HH; c += 32) {
            float v = hs[r][c] * sc;
            __nv_bfloat16 vh, vl;
            bsplit(v, &vh, &vl);
            g_hh[(size_t)(m0 + r) * HH + c] = vh;
            g_hl[(size_t)(m0 + r) * HH + c] = vl;
        }
    }
}

// ---------------- Wx -> transposed bf16 splits [n][k], tiled ----------------
__global__ void convW(const float* __restrict__ W, int layer) {
    __shared__ float tile[32][33];
    const int tx = threadIdx.x & 31, ty4 = (threadIdx.x >> 5) * 4;
    const int n0 = blockIdx.x * 32, k0 = blockIdx.y * 32;
#pragma unroll
    for (int r = 0; r < 4; r++)
        tile[ty4 + r][tx] = W[(size_t)(k0 + ty4 + r) * G4 + n0 + tx];
    __syncthreads();
#pragma unroll
    for (int r = 0; r < 4; r++) {
        int n = n0 + ty4 + r;
        float w = tile[tx][ty4 + r];
        __nv_bfloat16 h_, l_;
        bsplit(w, &h_, &l_);
        g_Wxh[layer][(size_t)n * HH + k0 + tx] = h_;
        g_Wxl[layer][(size_t)n * HH + k0 + tx] = l_;
    }
}

// ---------------- xg GEMM: 3-stage cp.async, XOR-swizzled 64B rows ----------
// 256 thr, 8 warps (4m x 2n), warp 32x64, Kc=32, distance-2 prefetch.
// SMEM row = 64B (32 bf16), 16B unit index swizzled: u' = u ^ (row & 3).
#define XG_ARR   8192                  // 128 rows * 64B
#define XG_STAGE (4 * XG_ARR)          // 32768
#define XG_SMEM  (3 * XG_STAGE)        // 98304

__global__ void __launch_bounds__(256, 2) gemm_xg(int layer, const float* __restrict__ bias) {
    const __nv_bfloat16* __restrict__ Ah = layer ? g_sh : g_hh;
    const __nv_bfloat16* __restrict__ Al = layer ? g_sl : g_hl;
    const __nv_bfloat16* __restrict__ Bh = g_Wxh[layer];
    const __nv_bfloat16* __restrict__ Bl = g_Wxl[layer];

    extern __shared__ __align__(16) uint8_t smd[];
    const int tid = threadIdx.x;
    const int lane = tid & 31, wid = tid >> 5;
    const int n0 = blockIdx.x * 128, m0 = blockIdx.y * 128;
    const int m_off = (wid >> 1) * 32, n_off = (wid & 1) * 64;
    const int lr = lane >> 2, lc = (lane & 3) * 2;
    const int r4 = lane & 3, rl = lane & 15, hi2 = lane >> 4;

    float acc[2][8][4];
#pragma unroll
    for (int i = 0; i < 2; i++)
#pragma unroll
        for (int j = 0; j < 8; j++)
#pragma unroll
            for (int q = 0; q < 4; q++) acc[i][j][q] = 0.f;

    const uint32_t smb = smem_u32(smd);
    // copy mapping: 2048 cp16 per stage, 8 per thread; swizzled destination
    const __nv_bfloat16* srcs[8];
    uint32_t dsts[8];
#pragma unroll
    for (int j = 0; j < 8; j++) {
        int id = tid + 256 * j;
        int arr = id >> 9, row = (id >> 2) & 127, seg = id & 3;
        const __nv_bfloat16* base =
            (arr == 0 ? Ah + (size_t)(m0 + row) * HH :
             arr == 1 ? Al + (size_t)(m0 + row) * HH :
             arr == 2 ? Bh + (size_t)(n0 + row) * HH :
                        Bl + (size_t)(n0 + row) * HH);
        srcs[j] = base + seg * 8;
        dsts[j] = smb + arr * XG_ARR + row * 64 + ((seg ^ (row & 3)) << 4);
    }

    // prologue: chunks 0, 1 into buffers 0, 1
#pragma unroll
    for (int j = 0; j < 8; j++) cp16(dsts[j], srcs[j]);
    CP_COMMIT();
#pragma unroll
    for (int j = 0; j < 8; j++) cp16(dsts[j] + XG_STAGE, srcs[j] + 32);
    CP_COMMIT();

    int bufc = 0;  // buffer holding current chunk
    for (int kc = 0; kc < HH; kc += 32) {
        if (kc + 32 < HH) CP_WAIT1(); else CP_WAIT0();
        __syncthreads();
        // issue chunk +2 into the buffer freed last iteration
        if (kc + 64 < HH) {
            int bufn = bufc >= 1 ? bufc - 1 : 2;  // (bufc + 2) % 3
#pragma unroll
            for (int j = 0; j < 8; j++)
                cp16(dsts[j] + bufn * XG_STAGE, srcs[j] + kc + 64);
            CP_COMMIT();
        }
        const uint32_t sb = smb + bufc * XG_STAGE;

#pragma unroll
        for (int ks = 0; ks < 32; ks += 16) {
            const int usw = (((ks >> 3) + hi2) ^ r4) << 4;  // swizzled 16B unit
            uint32_t afh[2][4], afl[2][4];
#pragma unroll
            for (int mi = 0; mi < 2; mi++) {
                uint32_t ar = sb + (m_off + mi * 16 + rl) * 64 + usw;
                ldsm4(afh[mi], ar);
                ldsm4(afl[mi], ar + XG_ARR);
            }
            uint32_t bfh[8][2], bfl[8][2];
#pragma unroll
            for (int g = 0; g < 4; g++) {
                uint32_t br = sb + 2 * XG_ARR + (n_off + g * 16 + rl) * 64 + usw;
                uint32_t tt[4];
                ldsm4(tt, br);
                bfh[2 * g][0] = tt[0]; bfh[2 * g + 1][0] = tt[1];
                bfh[2 * g][1] = tt[2]; bfh[2 * g + 1][1] = tt[3];
                ldsm4(tt, br + XG_ARR);
                bfl[2 * g][0] = tt[0]; bfl[2 * g + 1][0] = tt[1];
                bfl[2 * g][1] = tt[2]; bfl[2 * g + 1][1] = tt[3];
            }
#pragma unroll
            for (int mi = 0; mi < 2; mi++)
#pragma unroll
                for (int nf = 0; nf < 8; nf++) {
                    mma_bf16(acc[mi][nf], afh[mi], bfh[nf]);
                    mma_bf16(acc[mi][nf], afh[mi], bfl[nf]);
                    mma_bf16(acc[mi][nf], afl[mi], bfh[nf]);
                }
        }
        bufc = bufc < 2 ? bufc + 1 : 0;
    }

#pragma unroll
    for (int mi = 0; mi < 2; mi++)
#pragma unroll
        for (int nf = 0; nf < 8; nf++) {
            int r = m0 + m_off + mi * 16 + lr;
            int c = n0 + n_off + nf * 8 + lc;
            float2 bv = *(const float2*)&bias[c];
            *(float2*)&g_xg[(size_t)r * G4 + c] =
                make_float2(acc[mi][nf][0] + bv.x, acc[mi][nf][1] + bv.y);
            *(float2*)&g_xg[(size_t)(r + 8) * G4 + c] =
                make_float2(acc[mi][nf][2] + bv.x, acc[mi][nf][3] + bv.y);
        }
}

// ---------------- zero initial h splits ----------------
__global__ void zero_h() {
    int i = blockIdx.x * 256 + threadIdx.x;
    if (i < BB * HH / 2) {
        ((unsigned*)g_hpA)[i] = 0u;
        ((unsigned*)g_lpA)[i] = 0u;
    }
}

// ==================== persistent mma.sync LSTM (512 thr, K-split) ===========
// 128 blocks; block = 32 batch x 64 gate-cols. Warps 0-7: K[0,256), 8-15: K[256,512).
// Exact round-11 structure (xg prefetch at loop top, after the barrier).
#define L_BHI 0
#define L_BLO 66560
#define L_AHI 133120
#define L_ALO 166400
#define L_GS  199680
#define L_SMEM 216320

__global__ void __launch_bounds__(512, 1)
lstm_mma(const float* __restrict__ Wh, int layer) {
    extern __shared__ __align__(16) uint8_t sm[];
    const int tid = threadIdx.x, lane = tid & 31, wid = tid >> 5;
    const int grp = blockIdx.x >> 5;
    const int b0 = grp * 32;
    const int j0 = (blockIdx.x & 31) * 16;
    const int kh = wid >> 3;
    const int wq = wid & 7;
    const int m_off = (wq >> 2) * 16, n_off = (wq & 3) * 16;
    const int lr = lane >> 2, lc = (lane & 3) * 2;

    for (int i = tid; i < 64 * HH; i += 512) {
        int n = i & 63, k = i >> 6;
        float w = Wh[k * G4 + (n >> 4) * HH + j0 + (n & 15)];
        __nv_bfloat16 h_, l_;
        bsplit(w, &h_, &l_);
        *(__nv_bfloat16*)(sm + L_BHI + ((size_t)n * 520 + k) * 2) = h_;
        *(__nv_bfloat16*)(sm + L_BLO + ((size_t)n * 520 + k) * 2) = l_;
    }
    __syncthreads();

    float* Gs = (float*)(sm + L_GS);
    const uint32_t smb = smem_u32(sm);
    const int rr = tid >> 4, jj = tid & 15;
    const int tidl = tid & 255;
    const int kbase = kh * 256;
    float creg = 0.f;

    const uint32_t rAh = smb + L_AHI + (m_off + (lane & 15)) * 1040 + (lane >> 4) * 16 + kh * 512;
    const uint32_t rAl = smb + L_ALO + (m_off + (lane & 15)) * 1040 + (lane >> 4) * 16 + kh * 512;
    const uint32_t rBh = smb + L_BHI + (n_off + (lane & 15)) * 1040 + (lane >> 4) * 16 + kh * 512;
    const uint32_t rBl = smb + L_BLO + (n_off + (lane & 15)) * 1040 + (lane >> 4) * 16 + kh * 512;

    for (int t = 0; t < TT; t++) {
        const __nv_bfloat16* hph = (t & 1) ? g_hpB : g_hpA;
        const __nv_bfloat16* hpl = (t & 1) ? g_lpB : g_lpA;

        // xg prefetch (overlaps with the cp.async phase below)
        const float* xb = g_xg + ((size_t)(b0 + rr) * TT + t) * G4 + j0 + jj;
        float x0 = xb[0], x1 = xb[512], x2 = xb[1024], x3 = xb[1536];

        // each K-half warp-group loads ONLY its own half of the h tile
#pragma unroll
        for (int idx = tidl; idx < 1024; idx += 256) {
            int row = idx >> 5, k8 = (idx & 31) * 8 + kbase;
            cp16(smb + L_AHI + row * 1040 + k8 * 2, hph + (size_t)(b0 + row) * HH + k8);
            cp16(smb + L_ALO + row * 1040 + k8 * 2, hpl + (size_t)(b0 + row) * HH + k8);
        }
        CP_COMMIT();
        CP_WAIT0();
        asm volatile("bar.sync %0, 256;" :: "r"(4 + kh) : "memory");

        float acc[2][4] = {{0.f, 0.f, 0.f, 0.f}, {0.f, 0.f, 0.f, 0.f}};
#pragma unroll 2
        for (int kk = 0; kk < 256; kk += 16) {
            uint32_t ah[4], al[4], tb[4];
            uint32_t bh0[2], bh1[2], bl0[2], bl1[2];
            ldsm4(ah, rAh + kk * 2);
            ldsm4(al, rAl + kk * 2);
            ldsm4(tb, rBh + kk * 2);
            bh0[0] = tb[0]; bh1[0] = tb[1]; bh0[1] = tb[2]; bh1[1] = tb[3];
            ldsm4(tb, rBl + kk * 2);
            bl0[0] = tb[0]; bl1[0] = tb[1]; bl0[1] = tb[2]; bl1[1] = tb[3];
            mma_bf16(acc[0], ah, bh0);
            mma_bf16(acc[0], ah, bl0);
            mma_bf16(acc[0], al, bh0);
            mma_bf16(acc[1], ah, bh1);
            mma_bf16(acc[1], ah, bl1);
            mma_bf16(acc[1], al, bh1);
        }
        {
            float* Gk = Gs + kh * (32 * 65);
#pragma unroll
            for (int nf = 0; nf < 2; nf++) {
                int r = m_off + lr, c = n_off + nf * 8 + lc;
                Gk[r * 65 + c] = acc[nf][0];
                Gk[r * 65 + c + 1] = acc[nf][1];
                Gk[(r + 8) * 65 + c] = acc[nf][2];
                Gk[(r + 8) * 65 + c + 1] = acc[nf][3];
            }
        }
        __syncthreads();

        __nv_bfloat16* hnh = (t & 1) ? g_hpA : g_hpB;
        __nv_bfloat16* hnl = (t & 1) ? g_lpA : g_lpB;
        {
            float iv = Gs[rr * 65 + jj] + Gs[32 * 65 + rr * 65 + jj] + x0;
            float fv = Gs[rr * 65 + 16 + jj] + Gs[32 * 65 + rr * 65 + 16 + jj] + x1;
            float cv = Gs[rr * 65 + 32 + jj] + Gs[32 * 65 + rr * 65 + 32 + jj] + x2;
            float ov = Gs[rr * 65 + 48 + jj] + Gs[32 * 65 + rr * 65 + 48 + jj] + x3;
            iv = fsigm(iv);
            fv = fsigm(fv);
            ov = fsigm(ov);
            cv = ftanh(cv);
            float c = fv * creg + iv * cv;
            creg = c;
            float h = ov * ftanh(c);
            __nv_bfloat16 vh, vl;
            bsplit(h, &vh, &vl);
            hnh[(size_t)(b0 + rr) * HH + j0 + jj] = vh;
            hnl[(size_t)(b0 + rr) * HH + j0 + jj] = vl;
            if (layer == 0) {
                g_sh[((size_t)(b0 + rr) * TT + t) * HH + j0 + jj] = vh;
                g_sl[((size_t)(b0 + rr) * TT + t) * HH + j0 + jj] = vl;
            } else if (t == TT - 1) {
                g_hfin[(size_t)(b0 + rr) * HH + j0 + jj] = h;
            }
        }
        if (t < TT - 1) grid_bar4(grp);
    }
}

// ---------------- layernorm (eps=1e-3) on g_hfin ----------------
__global__ void layernorm(const float* __restrict__ gamma, const float* __restrict__ beta) {
    const int b = blockIdx.x, tid = threadIdx.x;
    const float* __restrict__ h = &g_hfin[b * HH];
    __shared__ float red[8];
    __shared__ float bc_mu, bc_rs;
    float s = 0.f;
    for (int j = tid; j < HH; j += 256) s += h[j];
#pragma unroll
    for (int o = 16; o; o >>= 1) s += __shfl_xor_sync(0xffffffffu, s, o);
    if ((tid & 31) == 0) red[tid >> 5] = s;
    __syncthreads();
    if (tid == 0) {
        float ts = 0.f;
        for (int i = 0; i < 8; i++) ts += red[i];
        bc_mu = ts / (float)HH;
    }
    __syncthreads();
    float mu = bc_mu;
    float v = 0.f;
    for (int j = tid; j < HH; j += 256) { float dd = h[j] - mu; v += dd * dd; }
#pragma unroll
    for (int o = 16; o; o >>= 1) v += __shfl_xor_sync(0xffffffffu, v, o);
    __syncthreads();
    if ((tid & 31) == 0) red[tid >> 5] = v;
    __syncthreads();
    if (tid == 0) {
        float ts = 0.f;
        for (int i = 0; i < 8; i++) ts += red[i];
        bc_rs = rsqrtf(ts / (float)HH + 1e-3f);
    }
    __syncthreads();
    float rs = bc_rs;
    for (int j = tid; j < HH; j += 256)
        g_ln[b * HH + j] = (h[j] - mu) * rs * gamma[j] + beta[j];
}

// ---------------- dense2 + relu ----------------
__global__ void dense2(const float* __restrict__ W2, const float* __restrict__ b2) {
    const int b = blockIdx.x, c = threadIdx.x;
    const float* __restrict__ h = &g_ln[b * HH];
    float s = b2[c];
    for (int k = 0; k < HH; k++) s += h[k] * W2[k * 256 + c];
    g_d2[b * 256 + c] = fmaxf(s, 0.f);
}

// ---------------- dense3 ----------------
__global__ void dense3(const float* __restrict__ W3, const float* __restrict__ b3,
                       float* __restrict__ out) {
    const int b = blockIdx.x, tid = threadIdx.x;
    float s = g_d2[b * 256 + tid] * W3[tid];
#pragma unroll
    for (int o = 16; o; o >>= 1) s += __shfl_xor_sync(0xffffffffu, s, o);
    __shared__ float red[8];
    if ((tid & 31) == 0) red[tid >> 5] = s;
    __syncthreads();
    if (tid == 0) {
        float ts = 0.f;
        for (int i = 0; i < 8; i++) ts += red[i];
        out[b] = ts + b3[0];
    }
}

// ---------------- launch ----------------
extern "C" void kernel_launch(void* const* d_in, const int* in_sizes, int n_in,
                              void* d_out, int out_size) {
    const float* x     = (const float*)d_in[0];
    const float* W1    = (const float*)d_in[1];
    const float* b1    = (const float*)d_in[2];
    const float* Wx1   = (const float*)d_in[3];
    const float* Wh1   = (const float*)d_in[4];
    const float* bl1   = (const float*)d_in[5];
    const float* Wx2   = (const float*)d_in[6];
    const float* Wh2   = (const float*)d_in[7];
    const float* bl2   = (const float*)d_in[8];
    const float* gamma = (const float*)d_in[9];
    const float* beta  = (const float*)d_in[10];
    const float* W2    = (const float*)d_in[11];
    const float* b2    = (const float*)d_in[12];
    const float* W3    = (const float*)d_in[13];
    const float* b3    = (const float*)d_in[14];
    float* out = (float*)d_out;

    static int init_done = 0;
    if (!init_done) {
        cudaFuncSetAttribute(lstm_mma, cudaFuncAttributeMaxDynamicSharedMemorySize,
                             L_SMEM);
        cudaFuncSetAttribute(gemm_xg, cudaFuncAttributeMaxDynamicSharedMemorySize,
                             XG_SMEM);
        init_done = 1;
    }

    dense1_norm<<<(BB * TT) / 16, 256>>>(x, W1, b1);
    convW<<<dim3(G4 / 32, HH / 32), 256>>>(Wx1, 0);
    convW<<<dim3(G4 / 32, HH / 32), 256>>>(Wx2, 1);

    gemm_xg<<<dim3(G4 / 128, (BB * TT) / 128), 256, XG_SMEM>>>(0, bl1);
    zero_h<<<(BB * HH / 2 + 255) / 256, 256>>>();
    lstm_mma<<<NBLK, 512, L_SMEM>>>(Wh1, 0);

    gemm_xg<<<dim3(G4 / 128, (BB * TT) / 128), 256, XG_SMEM>>>(1, bl2);
    zero_h<<<(BB * HH / 2 + 255) / 256, 256>>>();
    lstm_mma<<<NBLK, 512, L_SMEM>>>(Wh2, 1);

    layernorm<<<BB, 256>>>(gamma, beta);
    dense2<<<BB, 256>>>(W2, b2);
    dense3<<<BB, 256>>>(W3, b3, out);
}

// round 16
// speedup vs baseline: 1.0808x; 1.0087x over previous
#include <cuda_runtime.h>
#include <cuda_bf16.h>
#include <math.h>
#include <stdint.h>

#define BB 128
#define TT 256
#define FF 64
#define HH 512
#define G4 2048
#define NBLK 128  // persistent LSTM grid

// ---------------- mma / ldmatrix / cp.async helpers (arch-generic) ----------
__device__ __forceinline__ void mma_bf16(float* d, const uint32_t* a, const uint32_t* b) {
    asm volatile(
        "mma.sync.aligned.m16n8k16.row.col.f32.bf16.bf16.f32 "
        "{%0,%1,%2,%3}, {%4,%5,%6,%7}, {%8,%9}, {%0,%1,%2,%3};"
        : "+f"(d[0]), "+f"(d[1]), "+f"(d[2]), "+f"(d[3])
        : "r"(a[0]), "r"(a[1]), "r"(a[2]), "r"(a[3]), "r"(b[0]), "r"(b[1]));
}
__device__ __forceinline__ void ldsm4(uint32_t* r, uint32_t addr) {
    asm volatile("ldmatrix.sync.aligned.m8n8.x4.shared.b16 {%0,%1,%2,%3}, [%4];"
        : "=r"(r[0]), "=r"(r[1]), "=r"(r[2]), "=r"(r[3]) : "r"(addr));
}
__device__ __forceinline__ uint32_t smem_u32(const void* p) {
    uint32_t a;
    asm("{ .reg .u64 t; cvta.to.shared.u64 t, %1; cvt.u32.u64 %0, t; }"
        : "=r"(a) : "l"(p));
    return a;
}
__device__ __forceinline__ void cp16(uint32_t dst, const void* src) {
    asm volatile("cp.async.cg.shared.global [%0], [%1], 16;"
        :: "r"(dst), "l"(src) : "memory");
}
#define CP_COMMIT() asm volatile("cp.async.commit_group;" ::: "memory")
#define CP_WAIT0()  asm volatile("cp.async.wait_group 0;" ::: "memory")
#define CP_WAIT1()  asm volatile("cp.async.wait_group 1;" ::: "memory")

__device__ __forceinline__ void bsplit(float w, __nv_bfloat16* hi, __nv_bfloat16* lo) {
    __nv_bfloat16 h = __float2bfloat16(w);
    *hi = h;
    *lo = __float2bfloat16(w - __bfloat162float(h));
}
__device__ __forceinline__ float fsigm(float x) {
    return __fdividef(1.f, 1.f + __expf(-x));
}
__device__ __forceinline__ float ftanh(float x) {
    x = fminf(fmaxf(x, -15.f), 15.f);
    float e = __expf(-2.f * x);
    return __fdividef(1.f - e, 1.f + e);
}

// ---------------- scratch ----------------
__device__ __nv_bfloat16 g_hh[BB * TT * HH], g_hl[BB * TT * HH];
__device__ __nv_bfloat16 g_sh[BB * TT * HH], g_sl[BB * TT * HH];
__device__ __nv_bfloat16 g_Wxh[2][G4 * HH], g_Wxl[2][G4 * HH];
__device__ float g_xg[(size_t)BB * TT * G4];
__device__ __nv_bfloat16 g_hpA[BB * HH], g_hpB[BB * HH];
__device__ __nv_bfloat16 g_lpA[BB * HH], g_lpB[BB * HH];
__device__ float g_hfin[BB * HH];
__device__ float g_ln[BB * HH];
__device__ float g_d2[BB * (HH / 2)];
__device__ unsigned g_cnt4[4];
__device__ unsigned g_gen4[4];

// ------- per-batch-group grid barrier: release-arrive / acquire-spin --------
__device__ __forceinline__ void grid_bar4(int grp) {
    __syncthreads();
    if (threadIdx.x == 0) {
        unsigned* cp = &g_cnt4[grp];
        unsigned* gp = &g_gen4[grp];
        unsigned gen;
        asm volatile("ld.acquire.gpu.u32 %0, [%1];" : "=r"(gen) : "l"(gp));
        unsigned old;
        asm volatile("atom.add.release.gpu.u32 %0, [%1], 1;" : "=r"(old) : "l"(cp) : "memory");
        if (old == 31u) {
            asm volatile("st.relaxed.gpu.u32 [%0], 0;" :: "l"(cp) : "memory");
            asm volatile("red.add.release.gpu.u32 [%0], 1;" :: "l"(gp) : "memory");
        } else {
            unsigned g2;
            do {
                asm volatile("ld.acquire.gpu.u32 %0, [%1];" : "=r"(g2) : "l"(gp));
            } while (g2 == gen);
        }
    }
    __syncthreads();
}

// ---------------- dense1 + L2-norm scale (writes bf16 splits) ---------------
__global__ void dense1_norm(const float* __restrict__ x, const float* __restrict__ W1,
                            const float* __restrict__ b1) {
    __shared__ float xs[16][FF];
    __shared__ float hs[16][HH];
    const int tid = threadIdx.x;
    const int m0 = blockIdx.x * 16;
    for (int i = tid; i < 16 * FF; i += 256)
        xs[i / FF][i % FF] = x[(m0 + i / FF) * FF + i % FF];
    __syncthreads();
    const int c0 = tid * 2;
    float a0[16], a1[16];
#pragma unroll
    for (int r = 0; r < 16; r++) { a0[r] = 0.f; a1[r] = 0.f; }
    for (int k = 0; k < FF; k++) {
        float w0 = W1[k * HH + c0], w1 = W1[k * HH + c0 + 1];
#pragma unroll
        for (int r = 0; r < 16; r++) { float xv = xs[r][k]; a0[r] += xv * w0; a1[r] += xv * w1; }
    }
    float bb0 = b1[c0], bb1 = b1[c0 + 1];
#pragma unroll
    for (int r = 0; r < 16; r++) { hs[r][c0] = a0[r] + bb0; hs[r][c0 + 1] = a1[r] + bb1; }
    __syncthreads();
    int wid = tid >> 5, lane = tid & 31;
#pragma unroll
    for (int rr = 0; rr < 2; rr++) {
        int r = wid * 2 + rr;
        float ss = 0.f;
        for (int c = lane; c < HH; c += 32) { float v = hs[r][c]; ss += v * v; }
#pragma unroll
        for (int o = 16; o; o >>= 1) ss += __shfl_xor_sync(0xffffffffu, ss, o);
        float sc = sqrtf((float)HH) / fmaxf(sqrtf(ss), 1e-12f);
        for (int c = lane; c < HH; c += 32) {
            float v = hs[r][c] * sc;
            __nv_bfloat16 vh, vl;
            bsplit(v, &vh, &vl);
            g_hh[(size_t)(m0 + r) * HH + c] = vh;
            g_hl[(size_t)(m0 + r) * HH + c] = vl;
        }
    }
}

// ---------------- Wx -> transposed bf16 splits [n][k], tiled ----------------
__global__ void convW(const float* __restrict__ W, int layer) {
    __shared__ float tile[32][33];
    const int tx = threadIdx.x & 31, ty4 = (threadIdx.x >> 5) * 4;
    const int n0 = blockIdx.x * 32, k0 = blockIdx.y * 32;
#pragma unroll
    for (int r = 0; r < 4; r++)
        tile[ty4 + r][tx] = W[(size_t)(k0 + ty4 + r) * G4 + n0 + tx];
    __syncthreads();
#pragma unroll
    for (int r = 0; r < 4; r++) {
        int n = n0 + ty4 + r;
        float w = tile[tx][ty4 + r];
        __nv_bfloat16 h_, l_;
        bsplit(w, &h_, &l_);
        g_Wxh[layer][(size_t)n * HH + k0 + tx] = h_;
        g_Wxl[layer][(size_t)n * HH + k0 + tx] = l_;
    }
}

// ---------------- xg GEMM: 3-stage cp.async, XOR-swizzled 64B rows ----------
#define XG_ARR   8192                  // 128 rows * 64B
#define XG_STAGE (4 * XG_ARR)          // 32768
#define XG_SMEM  (3 * XG_STAGE)        // 98304

__global__ void __launch_bounds__(256, 2) gemm_xg(int layer, const float* __restrict__ bias) {
    const __nv_bfloat16* __restrict__ Ah = layer ? g_sh : g_hh;
    const __nv_bfloat16* __restrict__ Al = layer ? g_sl : g_hl;
    const __nv_bfloat16* __restrict__ Bh = g_Wxh[layer];
    const __nv_bfloat16* __restrict__ Bl = g_Wxl[layer];

    extern __shared__ __align__(16) uint8_t smd[];
    const int tid = threadIdx.x;
    const int lane = tid & 31, wid = tid >> 5;
    const int n0 = blockIdx.x * 128, m0 = blockIdx.y * 128;
    const int m_off = (wid >> 1) * 32, n_off = (wid & 1) * 64;
    const int lr = lane >> 2, lc = (lane & 3) * 2;
    const int r4 = lane & 3, rl = lane & 15, hi2 = lane >> 4;

    float acc[2][8][4];
#pragma unroll
    for (int i = 0; i < 2; i++)
#pragma unroll
        for (int j = 0; j < 8; j++)
#pragma unroll
            for (int q = 0; q < 4; q++) acc[i][j][q] = 0.f;

    const uint32_t smb = smem_u32(smd);
    const __nv_bfloat16* srcs[8];
    uint32_t dsts[8];
#pragma unroll
    for (int j = 0; j < 8; j++) {
        int id = tid + 256 * j;
        int arr = id >> 9, row = (id >> 2) & 127, seg = id & 3;
        const __nv_bfloat16* base =
            (arr == 0 ? Ah + (size_t)(m0 + row) * HH :
             arr == 1 ? Al + (size_t)(m0 + row) * HH :
             arr == 2 ? Bh + (size_t)(n0 + row) * HH :
                        Bl + (size_t)(n0 + row) * HH);
        srcs[j] = base + seg * 8;
        dsts[j] = smb + arr * XG_ARR + row * 64 + ((seg ^ (row & 3)) << 4);
    }

#pragma unroll
    for (int j = 0; j < 8; j++) cp16(dsts[j], srcs[j]);
    CP_COMMIT();
#pragma unroll
    for (int j = 0; j < 8; j++) cp16(dsts[j] + XG_STAGE, srcs[j] + 32);
    CP_COMMIT();

    int bufc = 0;
    for (int kc = 0; kc < HH; kc += 32) {
        if (kc + 32 < HH) CP_WAIT1(); else CP_WAIT0();
        __syncthreads();
        if (kc + 64 < HH) {
            int bufn = bufc >= 1 ? bufc - 1 : 2;
#pragma unroll
            for (int j = 0; j < 8; j++)
                cp16(dsts[j] + bufn * XG_STAGE, srcs[j] + kc + 64);
            CP_COMMIT();
        }
        const uint32_t sb = smb + bufc * XG_STAGE;

#pragma unroll
        for (int ks = 0; ks < 32; ks += 16) {
            const int usw = (((ks >> 3) + hi2) ^ r4) << 4;
            uint32_t afh[2][4], afl[2][4];
#pragma unroll
            for (int mi = 0; mi < 2; mi++) {
                uint32_t ar = sb + (m_off + mi * 16 + rl) * 64 + usw;
                ldsm4(afh[mi], ar);
                ldsm4(afl[mi], ar + XG_ARR);
            }
            uint32_t bfh[8][2], bfl[8][2];
#pragma unroll
            for (int g = 0; g < 4; g++) {
                uint32_t br = sb + 2 * XG_ARR + (n_off + g * 16 + rl) * 64 + usw;
                uint32_t tt[4];
                ldsm4(tt, br);
                bfh[2 * g][0] = tt[0]; bfh[2 * g + 1][0] = tt[1];
                bfh[2 * g][1] = tt[2]; bfh[2 * g + 1][1] = tt[3];
                ldsm4(tt, br + XG_ARR);
                bfl[2 * g][0] = tt[0]; bfl[2 * g + 1][0] = tt[1];
                bfl[2 * g][1] = tt[2]; bfl[2 * g + 1][1] = tt[3];
            }
#pragma unroll
            for (int mi = 0; mi < 2; mi++)
#pragma unroll
                for (int nf = 0; nf < 8; nf++) {
                    mma_bf16(acc[mi][nf], afh[mi], bfh[nf]);
                    mma_bf16(acc[mi][nf], afh[mi], bfl[nf]);
                    mma_bf16(acc[mi][nf], afl[mi], bfh[nf]);
                }
        }
        bufc = bufc < 2 ? bufc + 1 : 0;
    }

#pragma unroll
    for (int mi = 0; mi < 2; mi++)
#pragma unroll
        for (int nf = 0; nf < 8; nf++) {
            int r = m0 + m_off + mi * 16 + lr;
            int c = n0 + n_off + nf * 8 + lc;
            float2 bv = *(const float2*)&bias[c];
            *(float2*)&g_xg[(size_t)r * G4 + c] =
                make_float2(acc[mi][nf][0] + bv.x, acc[mi][nf][1] + bv.y);
            *(float2*)&g_xg[(size_t)(r + 8) * G4 + c] =
                make_float2(acc[mi][nf][2] + bv.x, acc[mi][nf][3] + bv.y);
        }
}

// ---------------- zero initial h splits ----------------
__global__ void zero_h() {
    int i = blockIdx.x * 256 + threadIdx.x;
    if (i < BB * HH / 2) {
        ((unsigned*)g_hpA)[i] = 0u;
        ((unsigned*)g_lpA)[i] = 0u;
    }
}

// ==================== persistent mma.sync LSTM (512 thr, K-split) ===========
// 128 blocks; block = 32 batch x 64 gate-cols. Warps 0-7: K[0,256), 8-15: K[256,512).
// Split accumulators per term (hh/hl/lh) to cut the dependent HMMA chain 3x.
#define L_BHI 0
#define L_BLO 66560
#define L_AHI 133120
#define L_ALO 166400
#define L_GS  199680
#define L_SMEM 216320

__global__ void __launch_bounds__(512, 1)
lstm_mma(const float* __restrict__ Wh, int layer) {
    extern __shared__ __align__(16) uint8_t sm[];
    const int tid = threadIdx.x, lane = tid & 31, wid = tid >> 5;
    const int grp = blockIdx.x >> 5;
    const int b0 = grp * 32;
    const int j0 = (blockIdx.x & 31) * 16;
    const int kh = wid >> 3;
    const int wq = wid & 7;
    const int m_off = (wq >> 2) * 16, n_off = (wq & 3) * 16;
    const int lr = lane >> 2, lc = (lane & 3) * 2;

    for (int i = tid; i < 64 * HH; i += 512) {
        int n = i & 63, k = i >> 6;
        float w = Wh[k * G4 + (n >> 4) * HH + j0 + (n & 15)];
        __nv_bfloat16 h_, l_;
        bsplit(w, &h_, &l_);
        *(__nv_bfloat16*)(sm + L_BHI + ((size_t)n * 520 + k) * 2) = h_;
        *(__nv_bfloat16*)(sm + L_BLO + ((size_t)n * 520 + k) * 2) = l_;
    }
    __syncthreads();

    float* Gs = (float*)(sm + L_GS);
    const uint32_t smb = smem_u32(sm);
    const int rr = tid >> 4, jj = tid & 15;
    const int tidl = tid & 255;
    const int kbase = kh * 256;
    float creg = 0.f;

    const uint32_t rAh = smb + L_AHI + (m_off + (lane & 15)) * 1040 + (lane >> 4) * 16 + kh * 512;
    const uint32_t rAl = smb + L_ALO + (m_off + (lane & 15)) * 1040 + (lane >> 4) * 16 + kh * 512;
    const uint32_t rBh = smb + L_BHI + (n_off + (lane & 15)) * 1040 + (lane >> 4) * 16 + kh * 512;
    const uint32_t rBl = smb + L_BLO + (n_off + (lane & 15)) * 1040 + (lane >> 4) * 16 + kh * 512;

    for (int t = 0; t < TT; t++) {
        const __nv_bfloat16* hph = (t & 1) ? g_hpB : g_hpA;
        const __nv_bfloat16* hpl = (t & 1) ? g_lpB : g_lpA;

        // xg prefetch (overlaps with the cp.async phase below)
        const float* xb = g_xg + ((size_t)(b0 + rr) * TT + t) * G4 + j0 + jj;
        float x0 = xb[0], x1 = xb[512], x2 = xb[1024], x3 = xb[1536];

        // each K-half warp-group loads ONLY its own half of the h tile
#pragma unroll
        for (int idx = tidl; idx < 1024; idx += 256) {
            int row = idx >> 5, k8 = (idx & 31) * 8 + kbase;
            cp16(smb + L_AHI + row * 1040 + k8 * 2, hph + (size_t)(b0 + row) * HH + k8);
            cp16(smb + L_ALO + row * 1040 + k8 * 2, hpl + (size_t)(b0 + row) * HH + k8);
        }
        CP_COMMIT();
        CP_WAIT0();
        asm volatile("bar.sync %0, 256;" :: "r"(4 + kh) : "memory");

        // three independent accumulators per N-fragment: chain depth 16, not 48
        float ahh[2][4] = {{0.f}, {0.f}};
        float ahl[2][4] = {{0.f}, {0.f}};
        float alh[2][4] = {{0.f}, {0.f}};
#pragma unroll 2
        for (int kk = 0; kk < 256; kk += 16) {
            uint32_t ah[4], al[4], tb[4];
            uint32_t bh0[2], bh1[2], bl0[2], bl1[2];
            ldsm4(ah, rAh + kk * 2);
            ldsm4(al, rAl + kk * 2);
            ldsm4(tb, rBh + kk * 2);
            bh0[0] = tb[0]; bh1[0] = tb[1]; bh0[1] = tb[2]; bh1[1] = tb[3];
            ldsm4(tb, rBl + kk * 2);
            bl0[0] = tb[0]; bl1[0] = tb[1]; bl0[1] = tb[2]; bl1[1] = tb[3];
            mma_bf16(ahh[0], ah, bh0);
            mma_bf16(ahl[0], ah, bl0);
            mma_bf16(alh[0], al, bh0);
            mma_bf16(ahh[1], ah, bh1);
            mma_bf16(ahl[1], ah, bl1);
            mma_bf16(alh[1], al, bh1);
        }
        {
            float* Gk = Gs + kh * (32 * 65);
#pragma unroll
            for (int nf = 0; nf < 2; nf++) {
                int r = m_off + lr, c = n_off + nf * 8 + lc;
                Gk[r * 65 + c]       = ahh[nf][0] + ahl[nf][0] + alh[nf][0];
                Gk[r * 65 + c + 1]   = ahh[nf][1] + ahl[nf][1] + alh[nf][1];
                Gk[(r + 8) * 65 + c]     = ahh[nf][2] + ahl[nf][2] + alh[nf][2];
                Gk[(r + 8) * 65 + c + 1] = ahh[nf][3] + ahl[nf][3] + alh[nf][3];
            }
        }
        __syncthreads();

        __nv_bfloat16* hnh = (t & 1) ? g_hpA : g_hpB;
        __nv_bfloat16* hnl = (t & 1) ? g_lpA : g_lpB;
        {
            float iv = Gs[rr * 65 + jj] + Gs[32 * 65 + rr * 65 + jj] + x0;
            float fv = Gs[rr * 65 + 16 + jj] + Gs[32 * 65 + rr * 65 + 16 + jj] + x1;
            float cv = Gs[rr * 65 + 32 + jj] + Gs[32 * 65 + rr * 65 + 32 + jj] + x2;
            float ov = Gs[rr * 65 + 48 + jj] + Gs[32 * 65 + rr * 65 + 48 + jj] + x3;
            iv = fsigm(iv);
            fv = fsigm(fv);
            ov = fsigm(ov);
            cv = ftanh(cv);
            float c = fv * creg + iv * cv;
            creg = c;
            float h = ov * ftanh(c);
            __nv_bfloat16 vh, vl;
            bsplit(h, &vh, &vl);
            hnh[(size_t)(b0 + rr) * HH + j0 + jj] = vh;
            hnl[(size_t)(b0 + rr) * HH + j0 + jj] = vl;
            if (layer == 0) {
                g_sh[((size_t)(b0 + rr) * TT + t) * HH + j0 + jj] = vh;
                g_sl[((size_t)(b0 + rr) * TT + t) * HH + j0 + jj] = vl;
            } else if (t == TT - 1) {
                g_hfin[(size_t)(b0 + rr) * HH + j0 + jj] = h;
            }
        }
        if (t < TT - 1) grid_bar4(grp);
    }
}

// ---------------- layernorm (eps=1e-3) on g_hfin ----------------
__global__ void layernorm(const float* __restrict__ gamma, const float* __restrict__ beta) {
    const int b = blockIdx.x, tid = threadIdx.x;
    const float* __restrict__ h = &g_hfin[b * HH];
    __shared__ float red[8];
    __shared__ float bc_mu, bc_rs;
    float s = 0.f;
    for (int j = tid; j < HH; j += 256) s += h[j];
#pragma unroll
    for (int o = 16; o; o >>= 1) s += __shfl_xor_sync(0xffffffffu, s, o);
    if ((tid & 31) == 0) red[tid >> 5] = s;
    __syncthreads();
    if (tid == 0) {
        float ts = 0.f;
        for (int i = 0; i < 8; i++) ts += red[i];
        bc_mu = ts / (float)HH;
    }
    __syncthreads();
    float mu = bc_mu;
    float v = 0.f;
    for (int j = tid; j < HH; j += 256) { float dd = h[j] - mu; v += dd * dd; }
#pragma unroll
    for (int o = 16; o; o >>= 1) v += __shfl_xor_sync(0xffffffffu, v, o);
    __syncthreads();
    if ((tid & 31) == 0) red[tid >> 5] = v;
    __syncthreads();
    if (tid == 0) {
        float ts = 0.f;
        for (int i = 0; i < 8; i++) ts += red[i];
        bc_rs = rsqrtf(ts / (float)HH + 1e-3f);
    }
    __syncthreads();
    float rs = bc_rs;
    for (int j = tid; j < HH; j += 256)
        g_ln[b * HH + j] = (h[j] - mu) * rs * gamma[j] + beta[j];
}

// ---------------- dense2 + relu ----------------
__global__ void dense2(const float* __restrict__ W2, const float* __restrict__ b2) {
    const int b = blockIdx.x, c = threadIdx.x;
    const float* __restrict__ h = &g_ln[b * HH];
    float s = b2[c];
    for (int k = 0; k < HH; k++) s += h[k] * W2[k * 256 + c];
    g_d2[b * 256 + c] = fmaxf(s, 0.f);
}

// ---------------- dense3 ----------------
__global__ void dense3(const float* __restrict__ W3, const float* __restrict__ b3,
                       float* __restrict__ out) {
    const int b = blockIdx.x, tid = threadIdx.x;
    float s = g_d2[b * 256 + tid] * W3[tid];
#pragma unroll
    for (int o = 16; o; o >>= 1) s += __shfl_xor_sync(0xffffffffu, s, o);
    __shared__ float red[8];
    if ((tid & 31) == 0) red[tid >> 5] = s;
    __syncthreads();
    if (tid == 0) {
        float ts = 0.f;
        for (int i = 0; i < 8; i++) ts += red[i];
        out[b] = ts + b3[0];
    }
}

// ---------------- launch ----------------
extern "C" void kernel_launch(void* const* d_in, const int* in_sizes, int n_in,
                              void* d_out, int out_size) {
    const float* x     = (const float*)d_in[0];
    const float* W1    = (const float*)d_in[1];
    const float* b1    = (const float*)d_in[2];
    const float* Wx1   = (const float*)d_in[3];
    const float* Wh1   = (const float*)d_in[4];
    const float* bl1   = (const float*)d_in[5];
    const float* Wx2   = (const float*)d_in[6];
    const float* Wh2   = (const float*)d_in[7];
    const float* bl2   = (const float*)d_in[8];
    const float* gamma = (const float*)d_in[9];
    const float* beta  = (const float*)d_in[10];
    const float* W2    = (const float*)d_in[11];
    const float* b2    = (const float*)d_in[12];
    const float* W3    = (const float*)d_in[13];
    const float* b3    = (const float*)d_in[14];
    float* out = (float*)d_out;

    static int init_done = 0;
    if (!init_done) {
        cudaFuncSetAttribute(lstm_mma, cudaFuncAttributeMaxDynamicSharedMemorySize,
                             L_SMEM);
        cudaFuncSetAttribute(gemm_xg, cudaFuncAttributeMaxDynamicSharedMemorySize,
                             XG_SMEM);
        init_done = 1;
    }

    dense1_norm<<<(BB * TT) / 16, 256>>>(x, W1, b1);
    convW<<<dim3(G4 / 32, HH / 32), 256>>>(Wx1, 0);
    convW<<<dim3(G4 / 32, HH / 32), 256>>>(Wx2, 1);

    gemm_xg<<<dim3(G4 / 128, (BB * TT) / 128), 256, XG_SMEM>>>(0, bl1);
    zero_h<<<(BB * HH / 2 + 255) / 256, 256>>>();
    lstm_mma<<<NBLK, 512, L_SMEM>>>(Wh1, 0);

    gemm_xg<<<dim3(G4 / 128, (BB * TT) / 128), 256, XG_SMEM>>>(1, bl2);
    zero_h<<<(BB * HH / 2 + 255) / 256, 256>>>();
    lstm_mma<<<NBLK, 512, L_SMEM>>>(Wh2, 1);

    layernorm<<<BB, 256>>>(gamma, beta);
    dense2<<<BB, 256>>>(W2, b2);
    dense3<<<BB, 256>>>(W3, b3, out);
}

// round 17
// speedup vs baseline: 1.0829x; 1.0020x over previous
#include <cuda_runtime.h>
#include <cuda_bf16.h>
#include <math.h>
#include <stdint.h>

#define BB 128
#define TT 256
#define FF 64
#define HH 512
#define G4 2048
#define NBLK 128  // persistent LSTM grid

// ---------------- mma / ldmatrix / cp.async helpers (arch-generic) ----------
__device__ __forceinline__ void mma_bf16(float* d, const uint32_t* a, const uint32_t* b) {
    asm volatile(
        "mma.sync.aligned.m16n8k16.row.col.f32.bf16.bf16.f32 "
        "{%0,%1,%2,%3}, {%4,%5,%6,%7}, {%8,%9}, {%0,%1,%2,%3};"
        : "+f"(d[0]), "+f"(d[1]), "+f"(d[2]), "+f"(d[3])
        : "r"(a[0]), "r"(a[1]), "r"(a[2]), "r"(a[3]), "r"(b[0]), "r"(b[1]));
}
__device__ __forceinline__ void ldsm4(uint32_t* r, uint32_t addr) {
    asm volatile("ldmatrix.sync.aligned.m8n8.x4.shared.b16 {%0,%1,%2,%3}, [%4];"
        : "=r"(r[0]), "=r"(r[1]), "=r"(r[2]), "=r"(r[3]) : "r"(addr));
}
__device__ __forceinline__ uint32_t smem_u32(const void* p) {
    uint32_t a;
    asm("{ .reg .u64 t; cvta.to.shared.u64 t, %1; cvt.u32.u64 %0, t; }"
        : "=r"(a) : "l"(p));
    return a;
}
__device__ __forceinline__ void cp16(uint32_t dst, const void* src) {
    asm volatile("cp.async.cg.shared.global [%0], [%1], 16;"
        :: "r"(dst), "l"(src) : "memory");
}
#define CP_COMMIT() asm volatile("cp.async.commit_group;" ::: "memory")
#define CP_WAIT0()  asm volatile("cp.async.wait_group 0;" ::: "memory")
#define CP_WAIT1()  asm volatile("cp.async.wait_group 1;" ::: "memory")

__device__ __forceinline__ void bsplit(float w, __nv_bfloat16* hi, __nv_bfloat16* lo) {
    __nv_bfloat16 h = __float2bfloat16(w);
    *hi = h;
    *lo = __float2bfloat16(w - __bfloat162float(h));
}
__device__ __forceinline__ float fsigm(float x) {
    return __fdividef(1.f, 1.f + __expf(-x));
}
__device__ __forceinline__ float ftanh(float x) {
    x = fminf(fmaxf(x, -15.f), 15.f);
    float e = __expf(-2.f * x);
    return __fdividef(1.f - e, 1.f + e);
}

// ---------------- scratch ----------------
__device__ __nv_bfloat16 g_hh[BB * TT * HH], g_hl[BB * TT * HH];
__device__ __nv_bfloat16 g_sh[BB * TT * HH], g_sl[BB * TT * HH];
__device__ __nv_bfloat16 g_Wxh[2][G4 * HH], g_Wxl[2][G4 * HH];
__device__ float g_xg[(size_t)BB * TT * G4];
__device__ __nv_bfloat16 g_hpA[BB * HH], g_hpB[BB * HH];
__device__ __nv_bfloat16 g_lpA[BB * HH], g_lpB[BB * HH];
__device__ float g_hfin[BB * HH];
__device__ float g_ln[BB * HH];
__device__ float g_d2[BB * (HH / 2)];
__device__ unsigned g_cnt4[4];
__device__ unsigned g_gen4[4];

// ------- per-batch-group grid barrier: release-arrive / acquire-spin --------
__device__ __forceinline__ void grid_bar4(int grp) {
    __syncthreads();
    if (threadIdx.x == 0) {
        unsigned* cp = &g_cnt4[grp];
        unsigned* gp = &g_gen4[grp];
        unsigned gen;
        asm volatile("ld.acquire.gpu.u32 %0, [%1];" : "=r"(gen) : "l"(gp));
        unsigned old;
        asm volatile("atom.add.release.gpu.u32 %0, [%1], 1;" : "=r"(old) : "l"(cp) : "memory");
        if (old == 31u) {
            asm volatile("st.relaxed.gpu.u32 [%0], 0;" :: "l"(cp) : "memory");
            asm volatile("red.add.release.gpu.u32 [%0], 1;" :: "l"(gp) : "memory");
        } else {
            unsigned g2;
            do {
                asm volatile("ld.acquire.gpu.u32 %0, [%1];" : "=r"(g2) : "l"(gp));
            } while (g2 == gen);
        }
    }
    __syncthreads();
}

// ---------------- dense1 + L2-norm scale (writes bf16 splits) ---------------
__global__ void dense1_norm(const float* __restrict__ x, const float* __restrict__ W1,
                            const float* __restrict__ b1) {
    __shared__ float xs[16][FF];
    __shared__ float hs[16][HH];
    const int tid = threadIdx.x;
    const int m0 = blockIdx.x * 16;
    for (int i = tid; i < 16 * FF; i += 256)
        xs[i / FF][i % FF] = x[(m0 + i / FF) * FF + i % FF];
    __syncthreads();
    const int c0 = tid * 2;
    float a0[16], a1[16];
#pragma unroll
    for (int r = 0; r < 16; r++) { a0[r] = 0.f; a1[r] = 0.f; }
    for (int k = 0; k < FF; k++) {
        float w0 = W1[k * HH + c0], w1 = W1[k * HH + c0 + 1];
#pragma unroll
        for (int r = 0; r < 16; r++) { float xv = xs[r][k]; a0[r] += xv * w0; a1[r] += xv * w1; }
    }
    float bb0 = b1[c0], bb1 = b1[c0 + 1];
#pragma unroll
    for (int r = 0; r < 16; r++) { hs[r][c0] = a0[r] + bb0; hs[r][c0 + 1] = a1[r] + bb1; }
    __syncthreads();
    int wid = tid >> 5, lane = tid & 31;
#pragma unroll
    for (int rr = 0; rr < 2; rr++) {
        int r = wid * 2 + rr;
        float ss = 0.f;
        for (int c = lane; c < HH; c += 32) { float v = hs[r][c]; ss += v * v; }
#pragma unroll
        for (int o = 16; o; o >>= 1) ss += __shfl_xor_sync(0xffffffffu, ss, o);
        float sc = sqrtf((float)HH) / fmaxf(sqrtf(ss), 1e-12f);
        for (int c = lane; c < HH; c += 32) {
            float v = hs[r][c] * sc;
            __nv_bfloat16 vh, vl;
            bsplit(v, &vh, &vl);
            g_hh[(size_t)(m0 + r) * HH + c] = vh;
            g_hl[(size_t)(m0 + r) * HH + c] = vl;
        }
    }
}

// ---------------- Wx -> transposed bf16 splits [n][k], tiled ----------------
__global__ void convW(const float* __restrict__ W, int layer) {
    __shared__ float tile[32][33];
    const int tx = threadIdx.x & 31, ty4 = (threadIdx.x >> 5) * 4;
    const int n0 = blockIdx.x * 32, k0 = blockIdx.y * 32;
#pragma unroll
    for (int r = 0; r < 4; r++)
        tile[ty4 + r][tx] = W[(size_t)(k0 + ty4 + r) * G4 + n0 + tx];
    __syncthreads();
#pragma unroll
    for (int r = 0; r < 4; r++) {
        int n = n0 + ty4 + r;
        float w = tile[tx][ty4 + r];
        __nv_bfloat16 h_, l_;
        bsplit(w, &h_, &l_);
        g_Wxh[layer][(size_t)n * HH + k0 + tx] = h_;
        g_Wxl[layer][(size_t)n * HH + k0 + tx] = l_;
    }
}

// ---------------- xg GEMM: 3-stage cp.async, XOR-swizzled 64B rows ----------
#define XG_ARR   8192                  // 128 rows * 64B
#define XG_STAGE (4 * XG_ARR)          // 32768
#define XG_SMEM  (3 * XG_STAGE)        // 98304

__global__ void __launch_bounds__(256, 2) gemm_xg(int layer, const float* __restrict__ bias) {
    const __nv_bfloat16* __restrict__ Ah = layer ? g_sh : g_hh;
    const __nv_bfloat16* __restrict__ Al = layer ? g_sl : g_hl;
    const __nv_bfloat16* __restrict__ Bh = g_Wxh[layer];
    const __nv_bfloat16* __restrict__ Bl = g_Wxl[layer];

    extern __shared__ __align__(16) uint8_t smd[];
    const int tid = threadIdx.x;
    const int lane = tid & 31, wid = tid >> 5;
    const int n0 = blockIdx.x * 128, m0 = blockIdx.y * 128;
    const int m_off = (wid >> 1) * 32, n_off = (wid & 1) * 64;
    const int lr = lane >> 2, lc = (lane & 3) * 2;
    const int r4 = lane & 3, rl = lane & 15, hi2 = lane >> 4;

    float acc[2][8][4];
#pragma unroll
    for (int i = 0; i < 2; i++)
#pragma unroll
        for (int j = 0; j < 8; j++)
#pragma unroll
            for (int q = 0; q < 4; q++) acc[i][j][q] = 0.f;

    const uint32_t smb = smem_u32(smd);
    const __nv_bfloat16* srcs[8];
    uint32_t dsts[8];
#pragma unroll
    for (int j = 0; j < 8; j++) {
        int id = tid + 256 * j;
        int arr = id >> 9, row = (id >> 2) & 127, seg = id & 3;
        const __nv_bfloat16* base =
            (arr == 0 ? Ah + (size_t)(m0 + row) * HH :
             arr == 1 ? Al + (size_t)(m0 + row) * HH :
             arr == 2 ? Bh + (size_t)(n0 + row) * HH :
                        Bl + (size_t)(n0 + row) * HH);
        srcs[j] = base + seg * 8;
        dsts[j] = smb + arr * XG_ARR + row * 64 + ((seg ^ (row & 3)) << 4);
    }

#pragma unroll
    for (int j = 0; j < 8; j++) cp16(dsts[j], srcs[j]);
    CP_COMMIT();
#pragma unroll
    for (int j = 0; j < 8; j++) cp16(dsts[j] + XG_STAGE, srcs[j] + 32);
    CP_COMMIT();

    int bufc = 0;
    for (int kc = 0; kc < HH; kc += 32) {
        if (kc + 32 < HH) CP_WAIT1(); else CP_WAIT0();
        __syncthreads();
        if (kc + 64 < HH) {
            int bufn = bufc >= 1 ? bufc - 1 : 2;
#pragma unroll
            for (int j = 0; j < 8; j++)
                cp16(dsts[j] + bufn * XG_STAGE, srcs[j] + kc + 64);
            CP_COMMIT();
        }
        const uint32_t sb = smb + bufc * XG_STAGE;

#pragma unroll
        for (int ks = 0; ks < 32; ks += 16) {
            const int usw = (((ks >> 3) + hi2) ^ r4) << 4;
            uint32_t afh[2][4], afl[2][4];
#pragma unroll
            for (int mi = 0; mi < 2; mi++) {
                uint32_t ar = sb + (m_off + mi * 16 + rl) * 64 + usw;
                ldsm4(afh[mi], ar);
                ldsm4(afl[mi], ar + XG_ARR);
            }
            uint32_t bfh[8][2], bfl[8][2];
#pragma unroll
            for (int g = 0; g < 4; g++) {
                uint32_t br = sb + 2 * XG_ARR + (n_off + g * 16 + rl) * 64 + usw;
                uint32_t tt[4];
                ldsm4(tt, br);
                bfh[2 * g][0] = tt[0]; bfh[2 * g + 1][0] = tt[1];
                bfh[2 * g][1] = tt[2]; bfh[2 * g + 1][1] = tt[3];
                ldsm4(tt, br + XG_ARR);
                bfl[2 * g][0] = tt[0]; bfl[2 * g + 1][0] = tt[1];
                bfl[2 * g][1] = tt[2]; bfl[2 * g + 1][1] = tt[3];
            }
#pragma unroll
            for (int mi = 0; mi < 2; mi++)
#pragma unroll
                for (int nf = 0; nf < 8; nf++) {
                    mma_bf16(acc[mi][nf], afh[mi], bfh[nf]);
                    mma_bf16(acc[mi][nf], afh[mi], bfl[nf]);
                    mma_bf16(acc[mi][nf], afl[mi], bfh[nf]);
                }
        }
        bufc = bufc < 2 ? bufc + 1 : 0;
    }

#pragma unroll
    for (int mi = 0; mi < 2; mi++)
#pragma unroll
        for (int nf = 0; nf < 8; nf++) {
            int r = m0 + m_off + mi * 16 + lr;
            int c = n0 + n_off + nf * 8 + lc;
            float2 bv = *(const float2*)&bias[c];
            *(float2*)&g_xg[(size_t)r * G4 + c] =
                make_float2(acc[mi][nf][0] + bv.x, acc[mi][nf][1] + bv.y);
            *(float2*)&g_xg[(size_t)(r + 8) * G4 + c] =
                make_float2(acc[mi][nf][2] + bv.x, acc[mi][nf][3] + bv.y);
        }
}

// ---------------- zero initial h splits ----------------
__global__ void zero_h() {
    int i = blockIdx.x * 256 + threadIdx.x;
    if (i < BB * HH / 2) {
        ((unsigned*)g_hpA)[i] = 0u;
        ((unsigned*)g_lpA)[i] = 0u;
    }
}

// ==================== persistent mma.sync LSTM (512 thr, K-split) ===========
// 128 blocks; block = 32 batch x 64 gate-cols. Warps 0-7: K[0,256), 8-15: K[256,512).
// Split accumulators + explicit fragment double-buffering in the K loop.
#define L_BHI 0
#define L_BLO 66560
#define L_AHI 133120
#define L_ALO 166400
#define L_GS  199680
#define L_SMEM 216320

__global__ void __launch_bounds__(512, 1)
lstm_mma(const float* __restrict__ Wh, int layer) {
    extern __shared__ __align__(16) uint8_t sm[];
    const int tid = threadIdx.x, lane = tid & 31, wid = tid >> 5;
    const int grp = blockIdx.x >> 5;
    const int b0 = grp * 32;
    const int j0 = (blockIdx.x & 31) * 16;
    const int kh = wid >> 3;
    const int wq = wid & 7;
    const int m_off = (wq >> 2) * 16, n_off = (wq & 3) * 16;
    const int lr = lane >> 2, lc = (lane & 3) * 2;

    for (int i = tid; i < 64 * HH; i += 512) {
        int n = i & 63, k = i >> 6;
        float w = Wh[k * G4 + (n >> 4) * HH + j0 + (n & 15)];
        __nv_bfloat16 h_, l_;
        bsplit(w, &h_, &l_);
        *(__nv_bfloat16*)(sm + L_BHI + ((size_t)n * 520 + k) * 2) = h_;
        *(__nv_bfloat16*)(sm + L_BLO + ((size_t)n * 520 + k) * 2) = l_;
    }
    __syncthreads();

    float* Gs = (float*)(sm + L_GS);
    const uint32_t smb = smem_u32(sm);
    const int rr = tid >> 4, jj = tid & 15;
    const int tidl = tid & 255;
    const int kbase = kh * 256;
    float creg = 0.f;

    const uint32_t rAh = smb + L_AHI + (m_off + (lane & 15)) * 1040 + (lane >> 4) * 16 + kh * 512;
    const uint32_t rAl = smb + L_ALO + (m_off + (lane & 15)) * 1040 + (lane >> 4) * 16 + kh * 512;
    const uint32_t rBh = smb + L_BHI + (n_off + (lane & 15)) * 1040 + (lane >> 4) * 16 + kh * 512;
    const uint32_t rBl = smb + L_BLO + (n_off + (lane & 15)) * 1040 + (lane >> 4) * 16 + kh * 512;

    for (int t = 0; t < TT; t++) {
        const __nv_bfloat16* hph = (t & 1) ? g_hpB : g_hpA;
        const __nv_bfloat16* hpl = (t & 1) ? g_lpB : g_lpA;

        // xg prefetch (overlaps with the cp.async phase below)
        const float* xb = g_xg + ((size_t)(b0 + rr) * TT + t) * G4 + j0 + jj;
        float x0 = xb[0], x1 = xb[512], x2 = xb[1024], x3 = xb[1536];

        // each K-half warp-group loads ONLY its own half of the h tile
#pragma unroll
        for (int idx = tidl; idx < 1024; idx += 256) {
            int row = idx >> 5, k8 = (idx & 31) * 8 + kbase;
            cp16(smb + L_AHI + row * 1040 + k8 * 2, hph + (size_t)(b0 + row) * HH + k8);
            cp16(smb + L_ALO + row * 1040 + k8 * 2, hpl + (size_t)(b0 + row) * HH + k8);
        }
        CP_COMMIT();
        CP_WAIT0();
        asm volatile("bar.sync %0, 256;" :: "r"(4 + kh) : "memory");

        // split accumulators (chain depth 16) + double-buffered fragments
        float ahh[2][4] = {{0.f}, {0.f}};
        float ahl[2][4] = {{0.f}, {0.f}};
        float alh[2][4] = {{0.f}, {0.f}};

        uint32_t ah[2][4], al[2][4], tbh[2][4], tbl[2][4];
        // preload chunk 0 into buffer 0
        ldsm4(ah[0], rAh);
        ldsm4(al[0], rAl);
        ldsm4(tbh[0], rBh);
        ldsm4(tbl[0], rBl);
#pragma unroll
        for (int c = 0; c < 16; c++) {
            const int cur = c & 1, nxt = cur ^ 1;
            if (c < 15) {
                const uint32_t off = (uint32_t)(c + 1) * 32;
                ldsm4(ah[nxt], rAh + off);
                ldsm4(al[nxt], rAl + off);
                ldsm4(tbh[nxt], rBh + off);
                ldsm4(tbl[nxt], rBl + off);
            }
            uint32_t bh0[2] = {tbh[cur][0], tbh[cur][2]};
            uint32_t bh1[2] = {tbh[cur][1], tbh[cur][3]};
            uint32_t bl0[2] = {tbl[cur][0], tbl[cur][2]};
            uint32_t bl1[2] = {tbl[cur][1], tbl[cur][3]};
            mma_bf16(ahh[0], ah[cur], bh0);
            mma_bf16(ahl[0], ah[cur], bl0);
            mma_bf16(alh[0], al[cur], bh0);
            mma_bf16(ahh[1], ah[cur], bh1);
            mma_bf16(ahl[1], ah[cur], bl1);
            mma_bf16(alh[1], al[cur], bh1);
        }
        {
            float* Gk = Gs + kh * (32 * 65);
#pragma unroll
            for (int nf = 0; nf < 2; nf++) {
                int r = m_off + lr, c = n_off + nf * 8 + lc;
                Gk[r * 65 + c]       = ahh[nf][0] + ahl[nf][0] + alh[nf][0];
                Gk[r * 65 + c + 1]   = ahh[nf][1] + ahl[nf][1] + alh[nf][1];
                Gk[(r + 8) * 65 + c]     = ahh[nf][2] + ahl[nf][2] + alh[nf][2];
                Gk[(r + 8) * 65 + c + 1] = ahh[nf][3] + ahl[nf][3] + alh[nf][3];
            }
        }
        __syncthreads();

        __nv_bfloat16* hnh = (t & 1) ? g_hpA : g_hpB;
        __nv_bfloat16* hnl = (t & 1) ? g_lpA : g_lpB;
        {
            float iv = Gs[rr * 65 + jj] + Gs[32 * 65 + rr * 65 + jj] + x0;
            float fv = Gs[rr * 65 + 16 + jj] + Gs[32 * 65 + rr * 65 + 16 + jj] + x1;
            float cv = Gs[rr * 65 + 32 + jj] + Gs[32 * 65 + rr * 65 + 32 + jj] + x2;
            float ov = Gs[rr * 65 + 48 + jj] + Gs[32 * 65 + rr * 65 + 48 + jj] + x3;
            iv = fsigm(iv);
            fv = fsigm(fv);
            ov = fsigm(ov);
            cv = ftanh(cv);
            float c = fv * creg + iv * cv;
            creg = c;
            float h = ov * ftanh(c);
            __nv_bfloat16 vh, vl;
            bsplit(h, &vh, &vl);
            hnh[(size_t)(b0 + rr) * HH + j0 + jj] = vh;
            hnl[(size_t)(b0 + rr) * HH + j0 + jj] = vl;
            if (layer == 0) {
                g_sh[((size_t)(b0 + rr) * TT + t) * HH + j0 + jj] = vh;
                g_sl[((size_t)(b0 + rr) * TT + t) * HH + j0 + jj] = vl;
            } else if (t == TT - 1) {
                g_hfin[(size_t)(b0 + rr) * HH + j0 + jj] = h;
            }
        }
        if (t < TT - 1) grid_bar4(grp);
    }
}

// ---------------- layernorm (eps=1e-3) on g_hfin ----------------
__global__ void layernorm(const float* __restrict__ gamma, const float* __restrict__ beta) {
    const int b = blockIdx.x, tid = threadIdx.x;
    const float* __restrict__ h = &g_hfin[b * HH];
    __shared__ float red[8];
    __shared__ float bc_mu, bc_rs;
    float s = 0.f;
    for (int j = tid; j < HH; j += 256) s += h[j];
#pragma unroll
    for (int o = 16; o; o >>= 1) s += __shfl_xor_sync(0xffffffffu, s, o);
    if ((tid & 31) == 0) red[tid >> 5] = s;
    __syncthreads();
    if (tid == 0) {
        float ts = 0.f;
        for (int i = 0; i < 8; i++) ts += red[i];
        bc_mu = ts / (float)HH;
    }
    __syncthreads();
    float mu = bc_mu;
    float v = 0.f;
    for (int j = tid; j < HH; j += 256) { float dd = h[j] - mu; v += dd * dd; }
#pragma unroll
    for (int o = 16; o; o >>= 1) v += __shfl_xor_sync(0xffffffffu, v, o);
    __syncthreads();
    if ((tid & 31) == 0) red[tid >> 5] = v;
    __syncthreads();
    if (tid == 0) {
        float ts = 0.f;
        for (int i = 0; i < 8; i++) ts += red[i];
        bc_rs = rsqrtf(ts / (float)HH + 1e-3f);
    }
    __syncthreads();
    float rs = bc_rs;
    for (int j = tid; j < HH; j += 256)
        g_ln[b * HH + j] = (h[j] - mu) * rs * gamma[j] + beta[j];
}

// ---------------- dense2 + relu ----------------
__global__ void dense2(const float* __restrict__ W2, const float* __restrict__ b2) {
    const int b = blockIdx.x, c = threadIdx.x;
    const float* __restrict__ h = &g_ln[b * HH];
    float s = b2[c];
    for (int k = 0; k < HH; k++) s += h[k] * W2[k * 256 + c];
    g_d2[b * 256 + c] = fmaxf(s, 0.f);
}

// ---------------- dense3 ----------------
__global__ void dense3(const float* __restrict__ W3, const float* __restrict__ b3,
                       float* __restrict__ out) {
    const int b = blockIdx.x, tid = threadIdx.x;
    float s = g_d2[b * 256 + tid] * W3[tid];
#pragma unroll
    for (int o = 16; o; o >>= 1) s += __shfl_xor_sync(0xffffffffu, s, o);
    __shared__ float red[8];
    if ((tid & 31) == 0) red[tid >> 5] = s;
    __syncthreads();
    if (tid == 0) {
        float ts = 0.f;
        for (int i = 0; i < 8; i++) ts += red[i];
        out[b] = ts + b3[0];
    }
}

// ---------------- launch ----------------
extern "C" void kernel_launch(void* const* d_in, const int* in_sizes, int n_in,
                              void* d_out, int out_size) {
    const float* x     = (const float*)d_in[0];
    const float* W1    = (const float*)d_in[1];
    const float* b1    = (const float*)d_in[2];
    const float* Wx1   = (const float*)d_in[3];
    const float* Wh1   = (const float*)d_in[4];
    const float* bl1   = (const float*)d_in[5];
    const float* Wx2   = (const float*)d_in[6];
    const float* Wh2   = (const float*)d_in[7];
    const float* bl2   = (const float*)d_in[8];
    const float* gamma = (const float*)d_in[9];
    const float* beta  = (const float*)d_in[10];
    const float* W2    = (const float*)d_in[11];
    const float* b2    = (const float*)d_in[12];
    const float* W3    = (const float*)d_in[13];
    const float* b3    = (const float*)d_in[14];
    float* out = (float*)d_out;

    static int init_done = 0;
    if (!init_done) {
        cudaFuncSetAttribute(lstm_mma, cudaFuncAttributeMaxDynamicSharedMemorySize,
                             L_SMEM);
        cudaFuncSetAttribute(gemm_xg, cudaFuncAttributeMaxDynamicSharedMemorySize,
                             XG_SMEM);
        init_done = 1;
    }

    dense1_norm<<<(BB * TT) / 16, 256>>>(x, W1, b1);
    convW<<<dim3(G4 / 32, HH / 32), 256>>>(Wx1, 0);
    convW<<<dim3(G4 / 32, HH / 32), 256>>>(Wx2, 1);

    gemm_xg<<<dim3(G4 / 128, (BB * TT) / 128), 256, XG_SMEM>>>(0, bl1);
    zero_h<<<(BB * HH / 2 + 255) / 256, 256>>>();
    lstm_mma<<<NBLK, 512, L_SMEM>>>(Wh1, 0);

    gemm_xg<<<dim3(G4 / 128, (BB * TT) / 128), 256, XG_SMEM>>>(1, bl2);
    zero_h<<<(BB * HH / 2 + 255) / 256, 256>>>();
    lstm_mma<<<NBLK, 512, L_SMEM>>>(Wh2, 1);

    layernorm<<<BB, 256>>>(gamma, beta);
    dense2<<<BB, 256>>>(W2, b2);
    dense3<<<BB, 256>>>(W3, b3, out);
}